// round 1
// baseline (speedup 1.0000x reference)
#include <cuda_runtime.h>
#include <math.h>

// ---------------- problem constants ----------------
#define BB 4
#define TT 4096
#define CC 1024
#define HH 16
#define NHD 64
#define QQ 256
#define NCK 16
#define MTOT (BB*TT)          // 16384
#define BTC (BB*TT*CC)        // 16777216
#define EPS_LN 1e-5f
#define EPS_GN (1e-5f*64.0f)

// ---------------- scratch (device globals; no cudaMalloc allowed) ----------------
// layout (float offsets):
//  0..15  : 16 buffers of BTC  (xln,xk,xv,xr,xg,r,k,v,g,y,yg,x1,xln2,xk2,xr2,hv)
//  16     : h buffer 3*BTC
//  then   : S, ST each B*H*NC*64*64 = 4194304
#define SCR_TOTAL (19ull*BTC + 2ull*4194304ull)
__device__ float g_scratch[SCR_TOTAL];

#define OFF_XLN  (0ull*BTC)
#define OFF_XK   (1ull*BTC)
#define OFF_XV   (2ull*BTC)
#define OFF_XR   (3ull*BTC)
#define OFF_XG   (4ull*BTC)
#define OFF_R    (5ull*BTC)
#define OFF_K    (6ull*BTC)
#define OFF_V    (7ull*BTC)
#define OFF_G    (8ull*BTC)
#define OFF_Y    (9ull*BTC)
#define OFF_YG   (10ull*BTC)
#define OFF_X1   (11ull*BTC)
#define OFF_XLN2 (12ull*BTC)
#define OFF_XK2  (13ull*BTC)
#define OFF_XR2  (14ull*BTC)
#define OFF_HV   (15ull*BTC)
#define OFF_H    (16ull*BTC)
#define OFF_S    (19ull*BTC)
#define OFF_ST   (19ull*BTC + 4194304ull)

// ---------------- LayerNorm: one block per (b,t) row ----------------
__global__ __launch_bounds__(256) void ln_kernel(const float* __restrict__ x,
                                                 const float* __restrict__ w,
                                                 const float* __restrict__ b,
                                                 float* __restrict__ out)
{
    int row = blockIdx.x;
    int tid = threadIdx.x;
    const float4* xr = (const float4*)(x + (size_t)row * CC);
    float4 v = xr[tid];
    float s  = v.x + v.y + v.z + v.w;
    float sq = v.x*v.x + v.y*v.y + v.z*v.z + v.w*v.w;
    #pragma unroll
    for (int o = 16; o >= 1; o >>= 1) {
        s  += __shfl_xor_sync(0xffffffffu, s,  o);
        sq += __shfl_xor_sync(0xffffffffu, sq, o);
    }
    __shared__ float ss[8], ssq[8];
    int wid = tid >> 5, lane = tid & 31;
    if (lane == 0) { ss[wid] = s; ssq[wid] = sq; }
    __syncthreads();
    if (tid == 0) {
        float a = 0.f, c2 = 0.f;
        #pragma unroll
        for (int i = 0; i < 8; i++) { a += ss[i]; c2 += ssq[i]; }
        ss[0] = a; ssq[0] = c2;
    }
    __syncthreads();
    float mu   = ss[0] * (1.0f / CC);
    float var  = ssq[0] * (1.0f / CC) - mu * mu;
    float rstd = rsqrtf(var + EPS_LN);
    float4 ww = ((const float4*)w)[tid];
    float4 bb = ((const float4*)b)[tid];
    float4 o4;
    o4.x = (v.x - mu) * rstd * ww.x + bb.x;
    o4.y = (v.y - mu) * rstd * ww.y + bb.y;
    o4.z = (v.z - mu) * rstd * ww.z + bb.z;
    o4.w = (v.w - mu) * rstd * ww.w + bb.w;
    ((float4*)(out + (size_t)row * CC))[tid] = o4;
}

// ---------------- time-mix interpolation (4 outputs) ----------------
__global__ __launch_bounds__(256) void tmix_mix_kernel(const float* __restrict__ xln,
                                                       const float* __restrict__ mk,
                                                       const float* __restrict__ mv,
                                                       const float* __restrict__ mr,
                                                       const float* __restrict__ mg,
                                                       float* __restrict__ xk,
                                                       float* __restrict__ xv,
                                                       float* __restrict__ xr,
                                                       float* __restrict__ xg)
{
    size_t i4 = (size_t)blockIdx.x * blockDim.x + threadIdx.x;   // over BTC/4
    int c4 = (int)(i4 % (CC / 4));
    size_t bt = i4 / (CC / 4);
    int t = (int)(bt % TT);
    float4 cur = ((const float4*)xln)[i4];
    float4 prev = make_float4(0.f, 0.f, 0.f, 0.f);
    if (t > 0) prev = ((const float4*)xln)[i4 - CC / 4];
    float4 xx = make_float4(prev.x - cur.x, prev.y - cur.y, prev.z - cur.z, prev.w - cur.w);
    float4 a, o;
    a = ((const float4*)mk)[c4];
    o.x = cur.x + xx.x * a.x; o.y = cur.y + xx.y * a.y; o.z = cur.z + xx.z * a.z; o.w = cur.w + xx.w * a.w;
    ((float4*)xk)[i4] = o;
    a = ((const float4*)mv)[c4];
    o.x = cur.x + xx.x * a.x; o.y = cur.y + xx.y * a.y; o.z = cur.z + xx.z * a.z; o.w = cur.w + xx.w * a.w;
    ((float4*)xv)[i4] = o;
    a = ((const float4*)mr)[c4];
    o.x = cur.x + xx.x * a.x; o.y = cur.y + xx.y * a.y; o.z = cur.z + xx.z * a.z; o.w = cur.w + xx.w * a.w;
    ((float4*)xr)[i4] = o;
    a = ((const float4*)mg)[c4];
    o.x = cur.x + xx.x * a.x; o.y = cur.y + xx.y * a.y; o.z = cur.z + xx.z * a.z; o.w = cur.w + xx.w * a.w;
    ((float4*)xg)[i4] = o;
}

// ---------------- channel-mix interpolation (2 outputs) ----------------
__global__ __launch_bounds__(256) void cmix_mix_kernel(const float* __restrict__ xln,
                                                       const float* __restrict__ mk,
                                                       const float* __restrict__ mr,
                                                       float* __restrict__ xk,
                                                       float* __restrict__ xr)
{
    size_t i4 = (size_t)blockIdx.x * blockDim.x + threadIdx.x;
    int c4 = (int)(i4 % (CC / 4));
    size_t bt = i4 / (CC / 4);
    int t = (int)(bt % TT);
    float4 cur = ((const float4*)xln)[i4];
    float4 prev = make_float4(0.f, 0.f, 0.f, 0.f);
    if (t > 0) prev = ((const float4*)xln)[i4 - CC / 4];
    float4 xx = make_float4(prev.x - cur.x, prev.y - cur.y, prev.z - cur.z, prev.w - cur.w);
    float4 a, o;
    a = ((const float4*)mk)[c4];
    o.x = cur.x + xx.x * a.x; o.y = cur.y + xx.y * a.y; o.z = cur.z + xx.z * a.z; o.w = cur.w + xx.w * a.w;
    ((float4*)xk)[i4] = o;
    a = ((const float4*)mr)[c4];
    o.x = cur.x + xx.x * a.x; o.y = cur.y + xx.y * a.y; o.z = cur.z + xx.z * a.z; o.w = cur.w + xx.w * a.w;
    ((float4*)xr)[i4] = o;
}

// ---------------- generic fp32 GEMM:  Cout[M,Nn] = A[M,K] @ W[Nn,K]^T  + epilogue ----------------
// epi: 0 plain, 1 silu, 2 relu^2, 3 sigmoid()*aux1+aux2, 4 +aux1
__global__ __launch_bounds__(256) void gemm_kernel(const float* __restrict__ A,
                                                   const float* __restrict__ W,
                                                   float* __restrict__ Co,
                                                   int Nn, int K, int epi,
                                                   const float* __restrict__ aux1,
                                                   const float* __restrict__ aux2)
{
    __shared__ float As[16][132];
    __shared__ float Ws[16][132];
    int tid = threadIdx.x;
    int n0 = blockIdx.x * 128;
    int m0 = blockIdx.y * 128;
    int ty = tid >> 4, tx = tid & 15;
    float acc[8][8];
    #pragma unroll
    for (int i = 0; i < 8; i++)
        #pragma unroll
        for (int j = 0; j < 8; j++) acc[i][j] = 0.f;

    const float* Ab = A + (size_t)m0 * K;
    const float* Wb = W + (size_t)n0 * K;

    for (int k0 = 0; k0 < K; k0 += 16) {
        __syncthreads();
        #pragma unroll
        for (int i = 0; i < 2; i++) {
            int idx = tid * 2 + i;
            int r  = idx >> 2;
            int fc = (idx & 3) * 4;
            float4 a4 = *(const float4*)(Ab + (size_t)r * K + k0 + fc);
            As[fc + 0][r] = a4.x; As[fc + 1][r] = a4.y; As[fc + 2][r] = a4.z; As[fc + 3][r] = a4.w;
            float4 w4 = *(const float4*)(Wb + (size_t)r * K + k0 + fc);
            Ws[fc + 0][r] = w4.x; Ws[fc + 1][r] = w4.y; Ws[fc + 2][r] = w4.z; Ws[fc + 3][r] = w4.w;
        }
        __syncthreads();
        #pragma unroll
        for (int kk = 0; kk < 16; kk++) {
            float4 a0 = *(const float4*)&As[kk][ty * 8];
            float4 a1 = *(const float4*)&As[kk][ty * 8 + 4];
            float4 b0 = *(const float4*)&Ws[kk][tx * 8];
            float4 b1 = *(const float4*)&Ws[kk][tx * 8 + 4];
            float av[8] = {a0.x, a0.y, a0.z, a0.w, a1.x, a1.y, a1.z, a1.w};
            float bv[8] = {b0.x, b0.y, b0.z, b0.w, b1.x, b1.y, b1.z, b1.w};
            #pragma unroll
            for (int i = 0; i < 8; i++)
                #pragma unroll
                for (int j = 0; j < 8; j++)
                    acc[i][j] += av[i] * bv[j];
        }
    }

    #pragma unroll
    for (int i = 0; i < 8; i++) {
        int m = m0 + ty * 8 + i;
        size_t rowo = (size_t)m * Nn + n0 + tx * 8;
        #pragma unroll
        for (int j = 0; j < 8; j++) {
            float vv = acc[i][j];
            size_t o = rowo + j;
            if (epi == 1) {
                vv = vv / (1.f + expf(-vv));                     // silu
            } else if (epi == 2) {
                vv = fmaxf(vv, 0.f); vv = vv * vv;               // relu^2
            } else if (epi == 3) {
                vv = 1.f / (1.f + expf(-vv));
                vv = vv * aux1[o] + aux2[o];                     // sigmoid * hv + x1
            } else if (epi == 4) {
                vv = vv + aux1[o];                               // + residual
            }
            Co[o] = vv;
        }
    }
}

// ---------------- WKV: per-chunk state contribution S = (k*wk) @ v ----------------
__global__ __launch_bounds__(256) void wkv_s_kernel(const float* __restrict__ k,
                                                    const float* __restrict__ v,
                                                    const float* __restrict__ decay,
                                                    float* __restrict__ S)
{
    int blk = blockIdx.x;                  // b*H*NC + h*NC + c
    int c = blk % NCK;
    int h = (blk / NCK) % HH;
    int b = blk / (NCK * HH);
    __shared__ float ksm[64][64];
    __shared__ float vsm[64][64];
    __shared__ float wpow[256];
    int tid = threadIdx.x;
    float ew = expf(decay[h]);
    wpow[tid] = expf(-ew * (float)tid);    // w^tid
    int n  = tid >> 2;
    int mg = (tid & 3) * 16;
    float acc[16];
    #pragma unroll
    for (int j = 0; j < 16; j++) acc[j] = 0.f;

    size_t base = ((size_t)b * TT + (size_t)c * QQ) * CC + (size_t)h * NHD;

    for (int qc = 0; qc < 4; qc++) {
        __syncthreads();
        for (int l = tid; l < 64 * 16; l += 256) {
            int qq = l >> 4;
            int f  = (l & 15) * 4;
            *(float4*)&ksm[qq][f] = *(const float4*)(k + base + (size_t)(qc * 64 + qq) * CC + f);
            *(float4*)&vsm[qq][f] = *(const float4*)(v + base + (size_t)(qc * 64 + qq) * CC + f);
        }
        __syncthreads();
        #pragma unroll 4
        for (int qq = 0; qq < 64; qq++) {
            float kw = ksm[qq][n] * wpow[255 - (qc * 64 + qq)];
            const float4* vr = (const float4*)&vsm[qq][mg];
            float4 v0 = vr[0], v1 = vr[1], v2 = vr[2], v3 = vr[3];
            acc[0]  += kw * v0.x; acc[1]  += kw * v0.y; acc[2]  += kw * v0.z; acc[3]  += kw * v0.w;
            acc[4]  += kw * v1.x; acc[5]  += kw * v1.y; acc[6]  += kw * v1.z; acc[7]  += kw * v1.w;
            acc[8]  += kw * v2.x; acc[9]  += kw * v2.y; acc[10] += kw * v2.z; acc[11] += kw * v2.w;
            acc[12] += kw * v3.x; acc[13] += kw * v3.y; acc[14] += kw * v3.z; acc[15] += kw * v3.w;
        }
    }
    float* Sp = S + (size_t)blk * 4096 + n * 64 + mg;
    #pragma unroll
    for (int j = 0; j < 16; j++) Sp[j] = acc[j];
}

// ---------------- WKV: inter-chunk prefix scan over states ----------------
__global__ __launch_bounds__(256) void wkv_scan_kernel(const float* __restrict__ S,
                                                       const float* __restrict__ decay,
                                                       float* __restrict__ ST)
{
    int bh = blockIdx.x;
    int h = bh % HH;
    float ws = expf(-expf(decay[h]) * 256.0f);  // w^Q
    int tid = threadIdx.x;
    size_t b0 = (size_t)bh * NCK * 4096;
    for (int r = 0; r < 16; r++) {
        int e = tid + r * 256;
        float st = 0.f;
        #pragma unroll
        for (int c = 0; c < NCK; c++) {
            ST[b0 + (size_t)c * 4096 + e] = st;
            st = ws * st + S[b0 + (size_t)c * 4096 + e];
        }
    }
}

// ---------------- WKV: per-chunk output  y = ((r@k)*Wm)@v + (r@state)*wb ----------------
#define WKV_Y_SMEM ((256*64*2 + 4096 + 256) * 4)
__global__ __launch_bounds__(256) void wkv_y_kernel(const float* __restrict__ r,
                                                    const float* __restrict__ k,
                                                    const float* __restrict__ v,
                                                    const float* __restrict__ ST,
                                                    const float* __restrict__ decay,
                                                    const float* __restrict__ faaaa,
                                                    float* __restrict__ y)
{
    extern __shared__ float sm[];
    float* ksm  = sm;                 // 256*64
    float* vsm  = sm + 16384;         // 256*64
    float* ssm  = sm + 32768;         // 64*64
    float* wpow = sm + 36864;         // 256

    int blk = blockIdx.x;
    int c = blk % NCK;
    int h = (blk / NCK) % HH;
    int b = blk / (NCK * HH);
    int tid = threadIdx.x;

    float ew = expf(decay[h]);
    float u  = faaaa[h];
    wpow[tid] = expf(-ew * (float)tid);

    size_t base = ((size_t)b * TT + (size_t)c * QQ) * CC + (size_t)h * NHD;

    for (int l = tid; l < 256 * 16; l += 256) {
        int qq = l >> 4;
        int f  = (l & 15) * 4;
        *(float4*)&ksm[qq * 64 + f] = *(const float4*)(k + base + (size_t)qq * CC + f);
        *(float4*)&vsm[qq * 64 + f] = *(const float4*)(v + base + (size_t)qq * CC + f);
    }
    size_t sbase = (size_t)blk * 4096;
    for (int l = tid; l < 1024; l += 256)
        *(float4*)&ssm[l * 4] = *(const float4*)(ST + sbase + (size_t)l * 4);
    __syncthreads();

    int q = tid;
    float rrow[64];
    {
        const float4* rg = (const float4*)(r + base + (size_t)q * CC);
        #pragma unroll
        for (int f = 0; f < 16; f++) {
            float4 t4 = rg[f];
            rrow[f * 4 + 0] = t4.x; rrow[f * 4 + 1] = t4.y;
            rrow[f * 4 + 2] = t4.z; rrow[f * 4 + 3] = t4.w;
        }
    }
    float acc[64];
    #pragma unroll
    for (int m = 0; m < 64; m++) acc[m] = 0.f;

    // (r @ state) — ssm reads are warp-uniform (broadcast)
    #pragma unroll 8
    for (int n = 0; n < 64; n++) {
        float rv = rrow[n];
        const float4* srow = (const float4*)&ssm[n * 64];
        #pragma unroll
        for (int m4 = 0; m4 < 16; m4++) {
            float4 s4 = srow[m4];
            acc[m4 * 4 + 0] += rv * s4.x;
            acc[m4 * 4 + 1] += rv * s4.y;
            acc[m4 * 4 + 2] += rv * s4.z;
            acc[m4 * 4 + 3] += rv * s4.w;
        }
    }
    float wbq = wpow[q];
    #pragma unroll
    for (int m = 0; m < 64; m++) acc[m] *= wbq;

    // intra-chunk: loop j to warp max; coef masks j>q lanes to 0
    int jend = q | 31;
    for (int j = 0; j <= jend; j++) {
        float a = 0.f;
        const float4* krow = (const float4*)&ksm[j * 64];
        #pragma unroll
        for (int n4 = 0; n4 < 16; n4++) {
            float4 k4 = krow[n4];
            a += rrow[n4 * 4 + 0] * k4.x + rrow[n4 * 4 + 1] * k4.y
               + rrow[n4 * 4 + 2] * k4.z + rrow[n4 * 4 + 3] * k4.w;
        }
        float coef = (j < q) ? wpow[q - j - 1] : ((j == q) ? u : 0.0f);
        a *= coef;
        const float4* vrow = (const float4*)&vsm[j * 64];
        #pragma unroll
        for (int m4 = 0; m4 < 16; m4++) {
            float4 v4 = vrow[m4];
            acc[m4 * 4 + 0] += a * v4.x;
            acc[m4 * 4 + 1] += a * v4.y;
            acc[m4 * 4 + 2] += a * v4.z;
            acc[m4 * 4 + 3] += a * v4.w;
        }
    }

    float* yo = y + base + (size_t)q * CC;
    #pragma unroll
    for (int m4 = 0; m4 < 16; m4++) {
        float4 o4 = make_float4(acc[m4 * 4 + 0], acc[m4 * 4 + 1], acc[m4 * 4 + 2], acc[m4 * 4 + 3]);
        *(float4*)(yo + m4 * 4) = o4;
    }
}

// ---------------- GroupNorm(64 per head) * g  ----------------
__global__ __launch_bounds__(256) void gn_mul_kernel(const float* __restrict__ y,
                                                     const float* __restrict__ gnw,
                                                     const float* __restrict__ gnb,
                                                     const float* __restrict__ g,
                                                     float* __restrict__ yg)
{
    int row = blockIdx.x;                // b*T + t
    int tid = threadIdx.x;               // 256; thread covers channels [4*tid, 4*tid+4)
    size_t off = (size_t)row * CC;
    float4 v = ((const float4*)(y + off))[tid];
    float s  = v.x + v.y + v.z + v.w;
    float sq = v.x*v.x + v.y*v.y + v.z*v.z + v.w*v.w;
    // reduce over the 16 threads of each head (64 channels)
    #pragma unroll
    for (int o = 8; o >= 1; o >>= 1) {
        s  += __shfl_xor_sync(0xffffffffu, s,  o);
        sq += __shfl_xor_sync(0xffffffffu, sq, o);
    }
    float mu   = s * (1.0f / 64.0f);
    float var  = sq * (1.0f / 64.0f) - mu * mu;
    float rstd = rsqrtf(var + EPS_GN);
    float4 ww = ((const float4*)gnw)[tid];
    float4 bb = ((const float4*)gnb)[tid];
    float4 gg = ((const float4*)(g + off))[tid];
    float4 o4;
    o4.x = ((v.x - mu) * rstd * ww.x + bb.x) * gg.x;
    o4.y = ((v.y - mu) * rstd * ww.y + bb.y) * gg.y;
    o4.z = ((v.z - mu) * rstd * ww.z + bb.z) * gg.z;
    o4.w = ((v.w - mu) * rstd * ww.w + bb.w) * gg.w;
    ((float4*)(yg + off))[tid] = o4;
}

// ---------------- host launcher ----------------
extern "C" void kernel_launch(void* const* d_in, const int* in_sizes, int n_in,
                              void* d_out, int out_size)
{
    const float* x      = (const float*)d_in[0];
    const float* ln1w   = (const float*)d_in[1];
    const float* ln1b   = (const float*)d_in[2];
    const float* maak   = (const float*)d_in[3];
    const float* maav   = (const float*)d_in[4];
    const float* maar   = (const float*)d_in[5];
    const float* maag   = (const float*)d_in[6];
    const float* decay  = (const float*)d_in[7];
    const float* faaaa  = (const float*)d_in[8];
    const float* Wr     = (const float*)d_in[9];
    const float* Wk     = (const float*)d_in[10];
    const float* Wv     = (const float*)d_in[11];
    const float* Wg     = (const float*)d_in[12];
    const float* Wo     = (const float*)d_in[13];
    const float* gnw    = (const float*)d_in[14];
    const float* gnb    = (const float*)d_in[15];
    const float* ln2w   = (const float*)d_in[16];
    const float* ln2b   = (const float*)d_in[17];
    const float* cmaak  = (const float*)d_in[18];
    const float* cmaar  = (const float*)d_in[19];
    const float* Wck    = (const float*)d_in[20];
    const float* Wcv    = (const float*)d_in[21];
    const float* Wcr    = (const float*)d_in[22];
    float* out = (float*)d_out;

    float* sc = nullptr;
    cudaGetSymbolAddress((void**)&sc, g_scratch);

    float* xln  = sc + OFF_XLN;
    float* xk   = sc + OFF_XK;
    float* xv   = sc + OFF_XV;
    float* xr   = sc + OFF_XR;
    float* xg   = sc + OFF_XG;
    float* rb   = sc + OFF_R;
    float* kb   = sc + OFF_K;
    float* vb   = sc + OFF_V;
    float* gb   = sc + OFF_G;
    float* yb   = sc + OFF_Y;
    float* ygb  = sc + OFF_YG;
    float* x1   = sc + OFF_X1;
    float* xln2 = sc + OFF_XLN2;
    float* xk2  = sc + OFF_XK2;
    float* xr2  = sc + OFF_XR2;
    float* hv   = sc + OFF_HV;
    float* hb   = sc + OFF_H;
    float* Sb   = sc + OFF_S;
    float* STb  = sc + OFF_ST;

    cudaFuncSetAttribute(wkv_y_kernel, cudaFuncAttributeMaxDynamicSharedMemorySize, WKV_Y_SMEM);

    dim3 g1024(1024 / 128, MTOT / 128);   // (8,128)
    dim3 g3072(3072 / 128, MTOT / 128);   // (24,128)
    int mixBlocks = BTC / 4 / 256;        // 16384

    // ---- time mix ----
    ln_kernel<<<MTOT, 256>>>(x, ln1w, ln1b, xln);
    tmix_mix_kernel<<<mixBlocks, 256>>>(xln, maak, maav, maar, maag, xk, xv, xr, xg);
    gemm_kernel<<<g1024, 256>>>(xr, Wr, rb, 1024, 1024, 0, nullptr, nullptr);
    gemm_kernel<<<g1024, 256>>>(xk, Wk, kb, 1024, 1024, 0, nullptr, nullptr);
    gemm_kernel<<<g1024, 256>>>(xv, Wv, vb, 1024, 1024, 0, nullptr, nullptr);
    gemm_kernel<<<g1024, 256>>>(xg, Wg, gb, 1024, 1024, 1, nullptr, nullptr);  // silu

    wkv_s_kernel<<<BB * HH * NCK, 256>>>(kb, vb, decay, Sb);
    wkv_scan_kernel<<<BB * HH, 256>>>(Sb, decay, STb);
    wkv_y_kernel<<<BB * HH * NCK, 256, WKV_Y_SMEM>>>(rb, kb, vb, STb, decay, faaaa, yb);

    gn_mul_kernel<<<MTOT, 256>>>(yb, gnw, gnb, gb, ygb);
    gemm_kernel<<<g1024, 256>>>(ygb, Wo, x1, 1024, 1024, 4, x, nullptr);       // + residual x

    // ---- channel mix ----
    ln_kernel<<<MTOT, 256>>>(x1, ln2w, ln2b, xln2);
    cmix_mix_kernel<<<mixBlocks, 256>>>(xln2, cmaak, cmaar, xk2, xr2);
    gemm_kernel<<<g3072, 256>>>(xk2, Wck, hb, 3072, 1024, 2, nullptr, nullptr); // relu^2
    gemm_kernel<<<g1024, 256>>>(hb, Wcv, hv, 1024, 3072, 0, nullptr, nullptr);
    gemm_kernel<<<g1024, 256>>>(xr2, Wcr, out, 1024, 1024, 3, hv, x1);          // sigmoid*hv + x1
}

// round 2
// speedup vs baseline: 2.8271x; 2.8271x over previous
#include <cuda_runtime.h>
#include <math.h>
#include <stdint.h>

// ---------------- problem constants ----------------
#define BB 4
#define TT 4096
#define CC 1024
#define HH 16
#define NHD 64
#define QQ 256
#define NCK 16
#define MTOT (BB*TT)          // 16384
#define BTC (BB*TT*CC)        // 16777216
#define EPS_LN 1e-5f
#define EPS_GN (1e-5f*64.0f)

// ---------------- scratch ----------------
#define SCR_TOTAL (19ull*BTC + 2ull*4194304ull)
__device__ float g_scratch[SCR_TOTAL];

#define OFF_XLN  (0ull*BTC)
#define OFF_XK   (1ull*BTC)
#define OFF_XV   (2ull*BTC)
#define OFF_XR   (3ull*BTC)
#define OFF_XG   (4ull*BTC)
#define OFF_R    (5ull*BTC)
#define OFF_K    (6ull*BTC)
#define OFF_V    (7ull*BTC)
#define OFF_G    (8ull*BTC)
#define OFF_Y    (9ull*BTC)
#define OFF_YG   (10ull*BTC)
#define OFF_X1   (11ull*BTC)
#define OFF_XLN2 (12ull*BTC)
#define OFF_XK2  (13ull*BTC)
#define OFF_XR2  (14ull*BTC)
#define OFF_HV   (15ull*BTC)
#define OFF_H    (16ull*BTC)
#define OFF_S    (19ull*BTC)
#define OFF_ST   (19ull*BTC + 4194304ull)

// ---------------- helpers ----------------
__device__ __forceinline__ float tf32_rna(float x) {
    uint32_t u;
    asm("cvt.rna.tf32.f32 %0, %1;" : "=r"(u) : "f"(x));
    return __uint_as_float(u);
}

// ---------------- LayerNorm ----------------
__global__ __launch_bounds__(256) void ln_kernel(const float* __restrict__ x,
                                                 const float* __restrict__ w,
                                                 const float* __restrict__ b,
                                                 float* __restrict__ out)
{
    int row = blockIdx.x;
    int tid = threadIdx.x;
    const float4* xr = (const float4*)(x + (size_t)row * CC);
    float4 v = xr[tid];
    float s  = v.x + v.y + v.z + v.w;
    float sq = v.x*v.x + v.y*v.y + v.z*v.z + v.w*v.w;
    #pragma unroll
    for (int o = 16; o >= 1; o >>= 1) {
        s  += __shfl_xor_sync(0xffffffffu, s,  o);
        sq += __shfl_xor_sync(0xffffffffu, sq, o);
    }
    __shared__ float ss[8], ssq[8];
    int wid = tid >> 5, lane = tid & 31;
    if (lane == 0) { ss[wid] = s; ssq[wid] = sq; }
    __syncthreads();
    if (tid == 0) {
        float a = 0.f, c2 = 0.f;
        #pragma unroll
        for (int i = 0; i < 8; i++) { a += ss[i]; c2 += ssq[i]; }
        ss[0] = a; ssq[0] = c2;
    }
    __syncthreads();
    float mu   = ss[0] * (1.0f / CC);
    float var  = ssq[0] * (1.0f / CC) - mu * mu;
    float rstd = rsqrtf(var + EPS_LN);
    float4 ww = ((const float4*)w)[tid];
    float4 bb = ((const float4*)b)[tid];
    float4 o4;
    o4.x = (v.x - mu) * rstd * ww.x + bb.x;
    o4.y = (v.y - mu) * rstd * ww.y + bb.y;
    o4.z = (v.z - mu) * rstd * ww.z + bb.z;
    o4.w = (v.w - mu) * rstd * ww.w + bb.w;
    ((float4*)(out + (size_t)row * CC))[tid] = o4;
}

// ---------------- time-mix interpolation ----------------
__global__ __launch_bounds__(256) void tmix_mix_kernel(const float* __restrict__ xln,
                                                       const float* __restrict__ mk,
                                                       const float* __restrict__ mv,
                                                       const float* __restrict__ mr,
                                                       const float* __restrict__ mg,
                                                       float* __restrict__ xk,
                                                       float* __restrict__ xv,
                                                       float* __restrict__ xr,
                                                       float* __restrict__ xg)
{
    size_t i4 = (size_t)blockIdx.x * blockDim.x + threadIdx.x;
    int c4 = (int)(i4 % (CC / 4));
    size_t bt = i4 / (CC / 4);
    int t = (int)(bt % TT);
    float4 cur = ((const float4*)xln)[i4];
    float4 prev = make_float4(0.f, 0.f, 0.f, 0.f);
    if (t > 0) prev = ((const float4*)xln)[i4 - CC / 4];
    float4 xx = make_float4(prev.x - cur.x, prev.y - cur.y, prev.z - cur.z, prev.w - cur.w);
    float4 a, o;
    a = ((const float4*)mk)[c4];
    o.x = cur.x + xx.x * a.x; o.y = cur.y + xx.y * a.y; o.z = cur.z + xx.z * a.z; o.w = cur.w + xx.w * a.w;
    ((float4*)xk)[i4] = o;
    a = ((const float4*)mv)[c4];
    o.x = cur.x + xx.x * a.x; o.y = cur.y + xx.y * a.y; o.z = cur.z + xx.z * a.z; o.w = cur.w + xx.w * a.w;
    ((float4*)xv)[i4] = o;
    a = ((const float4*)mr)[c4];
    o.x = cur.x + xx.x * a.x; o.y = cur.y + xx.y * a.y; o.z = cur.z + xx.z * a.z; o.w = cur.w + xx.w * a.w;
    ((float4*)xr)[i4] = o;
    a = ((const float4*)mg)[c4];
    o.x = cur.x + xx.x * a.x; o.y = cur.y + xx.y * a.y; o.z = cur.z + xx.z * a.z; o.w = cur.w + xx.w * a.w;
    ((float4*)xg)[i4] = o;
}

// ---------------- channel-mix interpolation ----------------
__global__ __launch_bounds__(256) void cmix_mix_kernel(const float* __restrict__ xln,
                                                       const float* __restrict__ mk,
                                                       const float* __restrict__ mr,
                                                       float* __restrict__ xk,
                                                       float* __restrict__ xr)
{
    size_t i4 = (size_t)blockIdx.x * blockDim.x + threadIdx.x;
    int c4 = (int)(i4 % (CC / 4));
    size_t bt = i4 / (CC / 4);
    int t = (int)(bt % TT);
    float4 cur = ((const float4*)xln)[i4];
    float4 prev = make_float4(0.f, 0.f, 0.f, 0.f);
    if (t > 0) prev = ((const float4*)xln)[i4 - CC / 4];
    float4 xx = make_float4(prev.x - cur.x, prev.y - cur.y, prev.z - cur.z, prev.w - cur.w);
    float4 a, o;
    a = ((const float4*)mk)[c4];
    o.x = cur.x + xx.x * a.x; o.y = cur.y + xx.y * a.y; o.z = cur.z + xx.z * a.z; o.w = cur.w + xx.w * a.w;
    ((float4*)xk)[i4] = o;
    a = ((const float4*)mr)[c4];
    o.x = cur.x + xx.x * a.x; o.y = cur.y + xx.y * a.y; o.z = cur.z + xx.z * a.z; o.w = cur.w + xx.w * a.w;
    ((float4*)xr)[i4] = o;
}

// ---------------- tf32 tensor-core GEMM ----------------
// Cout[M,Nn] = A[M,K] @ W[Nn,K]^T + epilogue.
// 128x128x32 tiles, 256 threads (8 warps = 2x4), warp tile 64x32 = 4x4 m16n8k8.
// Double-buffered dynamic smem: As/Bs row stride 36 floats (conflict-free frag loads).
// epi: 0 plain, 1 silu, 2 relu^2, 3 sigmoid()*aux1+aux2, 4 +aux1
#define GEMM_SMEM (4ull * 4608ull * 4ull)   // 73728 bytes

__device__ __forceinline__ void mma_tf32(float c[4],
                                         const uint32_t a[4],
                                         const uint32_t b[2])
{
    asm volatile(
        "mma.sync.aligned.m16n8k8.row.col.f32.tf32.tf32.f32 "
        "{%0,%1,%2,%3}, {%4,%5,%6,%7}, {%8,%9}, {%0,%1,%2,%3};\n"
        : "+f"(c[0]), "+f"(c[1]), "+f"(c[2]), "+f"(c[3])
        : "r"(a[0]), "r"(a[1]), "r"(a[2]), "r"(a[3]),
          "r"(b[0]), "r"(b[1]));
}

__device__ __forceinline__ float gemm_epi(float vv, int epi, const float* aux1,
                                          const float* aux2, size_t o)
{
    if (epi == 1) {
        vv = vv / (1.f + expf(-vv));
    } else if (epi == 2) {
        vv = fmaxf(vv, 0.f); vv = vv * vv;
    } else if (epi == 3) {
        vv = 1.f / (1.f + expf(-vv));
        vv = vv * aux1[o] + aux2[o];
    } else if (epi == 4) {
        vv = vv + aux1[o];
    }
    return vv;
}

__global__ __launch_bounds__(256) void gemm_tc_kernel(const float* __restrict__ A,
                                                      const float* __restrict__ W,
                                                      float* __restrict__ Co,
                                                      int Nn, int K, int epi,
                                                      const float* __restrict__ aux1,
                                                      const float* __restrict__ aux2)
{
    extern __shared__ float sm[];
    // layout: As0[4608], As1[4608], Bs0[4608], Bs1[4608]  (row stride 36)
    int tid = threadIdx.x;
    int n0 = blockIdx.x * 128;
    int m0 = blockIdx.y * 128;
    int wid = tid >> 5, lane = tid & 31;
    int wm = wid >> 2, wn = wid & 3;             // 2 x 4 warp grid
    int gid = lane >> 2, tg = lane & 3;

    const float* Ab = A + (size_t)m0 * K;
    const float* Wb = W + (size_t)n0 * K;

    int r_ld  = tid >> 3;          // 0..31  (row within 128 handled via +32*i)
    int fq_ld = (tid & 7) * 4;     // k-offset float

    float acc[4][4][4];
    #pragma unroll
    for (int mi = 0; mi < 4; mi++)
        #pragma unroll
        for (int ni = 0; ni < 4; ni++)
            #pragma unroll
            for (int e = 0; e < 4; e++) acc[mi][ni][e] = 0.f;

    int nK = K >> 5;

    // prologue: load stage 0
    {
        float* As = sm;
        float* Bs = sm + 9216;
        #pragma unroll
        for (int i = 0; i < 4; i++) {
            int r = r_ld + 32 * i;
            float4 a4 = *(const float4*)(Ab + (size_t)r * K + fq_ld);
            float4 w4 = *(const float4*)(Wb + (size_t)r * K + fq_ld);
            float* ap = As + r * 36 + fq_ld;
            ap[0] = tf32_rna(a4.x); ap[1] = tf32_rna(a4.y);
            ap[2] = tf32_rna(a4.z); ap[3] = tf32_rna(a4.w);
            float* bp = Bs + r * 36 + fq_ld;
            bp[0] = tf32_rna(w4.x); bp[1] = tf32_rna(w4.y);
            bp[2] = tf32_rna(w4.z); bp[3] = tf32_rna(w4.w);
        }
    }
    __syncthreads();

    for (int t = 0; t < nK; t++) {
        int cur = t & 1;
        float4 ra[4], rw[4];
        if (t + 1 < nK) {
            int kb = (t + 1) << 5;
            #pragma unroll
            for (int i = 0; i < 4; i++) {
                int r = r_ld + 32 * i;
                ra[i] = *(const float4*)(Ab + (size_t)r * K + kb + fq_ld);
                rw[i] = *(const float4*)(Wb + (size_t)r * K + kb + fq_ld);
            }
        }

        const float* As = sm + cur * 4608;
        const float* Bs = sm + 9216 + cur * 4608;

        #pragma unroll
        for (int kk = 0; kk < 4; kk++) {
            int ks = kk * 8;
            uint32_t af[4][4];
            uint32_t bf[4][2];
            #pragma unroll
            for (int mi = 0; mi < 4; mi++) {
                const float* ap = As + (wm * 64 + mi * 16 + gid) * 36 + ks + tg;
                af[mi][0] = __float_as_uint(ap[0]);
                af[mi][1] = __float_as_uint(ap[8 * 36]);
                af[mi][2] = __float_as_uint(ap[4]);
                af[mi][3] = __float_as_uint(ap[8 * 36 + 4]);
            }
            #pragma unroll
            for (int ni = 0; ni < 4; ni++) {
                const float* bp = Bs + (wn * 32 + ni * 8 + gid) * 36 + ks + tg;
                bf[ni][0] = __float_as_uint(bp[0]);
                bf[ni][1] = __float_as_uint(bp[4]);
            }
            #pragma unroll
            for (int mi = 0; mi < 4; mi++)
                #pragma unroll
                for (int ni = 0; ni < 4; ni++)
                    mma_tf32(acc[mi][ni], af[mi], bf[ni]);
        }

        if (t + 1 < nK) {
            float* Asn = sm + (cur ^ 1) * 4608;
            float* Bsn = sm + 9216 + (cur ^ 1) * 4608;
            #pragma unroll
            for (int i = 0; i < 4; i++) {
                int r = r_ld + 32 * i;
                float* ap = Asn + r * 36 + fq_ld;
                ap[0] = tf32_rna(ra[i].x); ap[1] = tf32_rna(ra[i].y);
                ap[2] = tf32_rna(ra[i].z); ap[3] = tf32_rna(ra[i].w);
                float* bp = Bsn + r * 36 + fq_ld;
                bp[0] = tf32_rna(rw[i].x); bp[1] = tf32_rna(rw[i].y);
                bp[2] = tf32_rna(rw[i].z); bp[3] = tf32_rna(rw[i].w);
            }
        }
        __syncthreads();
    }

    // epilogue
    #pragma unroll
    for (int mi = 0; mi < 4; mi++) {
        int row0 = m0 + wm * 64 + mi * 16 + gid;
        #pragma unroll
        for (int ni = 0; ni < 4; ni++) {
            int col0 = n0 + wn * 32 + ni * 8 + tg * 2;
            size_t o0 = (size_t)row0 * Nn + col0;
            size_t o1 = (size_t)(row0 + 8) * Nn + col0;
            float2 v0, v1;
            v0.x = gemm_epi(acc[mi][ni][0], epi, aux1, aux2, o0);
            v0.y = gemm_epi(acc[mi][ni][1], epi, aux1, aux2, o0 + 1);
            v1.x = gemm_epi(acc[mi][ni][2], epi, aux1, aux2, o1);
            v1.y = gemm_epi(acc[mi][ni][3], epi, aux1, aux2, o1 + 1);
            *(float2*)(Co + o0) = v0;
            *(float2*)(Co + o1) = v1;
        }
    }
}

// ---------------- WKV: per-chunk state contribution S = (k*wk) @ v ----------------
__global__ __launch_bounds__(256) void wkv_s_kernel(const float* __restrict__ k,
                                                    const float* __restrict__ v,
                                                    const float* __restrict__ decay,
                                                    float* __restrict__ S)
{
    int blk = blockIdx.x;
    int c = blk % NCK;
    int h = (blk / NCK) % HH;
    int b = blk / (NCK * HH);
    __shared__ float ksm[64][64];
    __shared__ float vsm[64][64];
    __shared__ float wpow[256];
    int tid = threadIdx.x;
    float ew = expf(decay[h]);
    wpow[tid] = expf(-ew * (float)tid);
    int n  = tid >> 2;
    int mg = (tid & 3) * 16;
    float acc[16];
    #pragma unroll
    for (int j = 0; j < 16; j++) acc[j] = 0.f;

    size_t base = ((size_t)b * TT + (size_t)c * QQ) * CC + (size_t)h * NHD;

    for (int qc = 0; qc < 4; qc++) {
        __syncthreads();
        for (int l = tid; l < 64 * 16; l += 256) {
            int qq = l >> 4;
            int f  = (l & 15) * 4;
            *(float4*)&ksm[qq][f] = *(const float4*)(k + base + (size_t)(qc * 64 + qq) * CC + f);
            *(float4*)&vsm[qq][f] = *(const float4*)(v + base + (size_t)(qc * 64 + qq) * CC + f);
        }
        __syncthreads();
        #pragma unroll 4
        for (int qq = 0; qq < 64; qq++) {
            float kw = ksm[qq][n] * wpow[255 - (qc * 64 + qq)];
            const float4* vr = (const float4*)&vsm[qq][mg];
            float4 v0 = vr[0], v1 = vr[1], v2 = vr[2], v3 = vr[3];
            acc[0]  += kw * v0.x; acc[1]  += kw * v0.y; acc[2]  += kw * v0.z; acc[3]  += kw * v0.w;
            acc[4]  += kw * v1.x; acc[5]  += kw * v1.y; acc[6]  += kw * v1.z; acc[7]  += kw * v1.w;
            acc[8]  += kw * v2.x; acc[9]  += kw * v2.y; acc[10] += kw * v2.z; acc[11] += kw * v2.w;
            acc[12] += kw * v3.x; acc[13] += kw * v3.y; acc[14] += kw * v3.z; acc[15] += kw * v3.w;
        }
    }
    float* Sp = S + (size_t)blk * 4096 + n * 64 + mg;
    #pragma unroll
    for (int j = 0; j < 16; j++) Sp[j] = acc[j];
}

// ---------------- WKV: inter-chunk prefix scan ----------------
__global__ __launch_bounds__(256) void wkv_scan_kernel(const float* __restrict__ S,
                                                       const float* __restrict__ decay,
                                                       float* __restrict__ ST)
{
    int bh = blockIdx.x;
    int h = bh % HH;
    float ws = expf(-expf(decay[h]) * 256.0f);
    int tid = threadIdx.x;
    size_t b0 = (size_t)bh * NCK * 4096;
    for (int r = 0; r < 16; r++) {
        int e = tid + r * 256;
        float st = 0.f;
        #pragma unroll
        for (int c = 0; c < NCK; c++) {
            ST[b0 + (size_t)c * 4096 + e] = st;
            st = ws * st + S[b0 + (size_t)c * 4096 + e];
        }
    }
}

// ---------------- WKV: per-chunk output ----------------
#define WKV_Y_SMEM ((256*64*2 + 4096 + 256) * 4)
__global__ __launch_bounds__(256) void wkv_y_kernel(const float* __restrict__ r,
                                                    const float* __restrict__ k,
                                                    const float* __restrict__ v,
                                                    const float* __restrict__ ST,
                                                    const float* __restrict__ decay,
                                                    const float* __restrict__ faaaa,
                                                    float* __restrict__ y)
{
    extern __shared__ float sm[];
    float* ksm  = sm;
    float* vsm  = sm + 16384;
    float* ssm  = sm + 32768;
    float* wpow = sm + 36864;

    int blk = blockIdx.x;
    int c = blk % NCK;
    int h = (blk / NCK) % HH;
    int b = blk / (NCK * HH);
    int tid = threadIdx.x;

    float ew = expf(decay[h]);
    float u  = faaaa[h];
    wpow[tid] = expf(-ew * (float)tid);

    size_t base = ((size_t)b * TT + (size_t)c * QQ) * CC + (size_t)h * NHD;

    for (int l = tid; l < 256 * 16; l += 256) {
        int qq = l >> 4;
        int f  = (l & 15) * 4;
        *(float4*)&ksm[qq * 64 + f] = *(const float4*)(k + base + (size_t)qq * CC + f);
        *(float4*)&vsm[qq * 64 + f] = *(const float4*)(v + base + (size_t)qq * CC + f);
    }
    size_t sbase = (size_t)blk * 4096;
    for (int l = tid; l < 1024; l += 256)
        *(float4*)&ssm[l * 4] = *(const float4*)(ST + sbase + (size_t)l * 4);
    __syncthreads();

    int q = tid;
    float rrow[64];
    {
        const float4* rg = (const float4*)(r + base + (size_t)q * CC);
        #pragma unroll
        for (int f = 0; f < 16; f++) {
            float4 t4 = rg[f];
            rrow[f * 4 + 0] = t4.x; rrow[f * 4 + 1] = t4.y;
            rrow[f * 4 + 2] = t4.z; rrow[f * 4 + 3] = t4.w;
        }
    }
    float acc[64];
    #pragma unroll
    for (int m = 0; m < 64; m++) acc[m] = 0.f;

    #pragma unroll 8
    for (int n = 0; n < 64; n++) {
        float rv = rrow[n];
        const float4* srow = (const float4*)&ssm[n * 64];
        #pragma unroll
        for (int m4 = 0; m4 < 16; m4++) {
            float4 s4 = srow[m4];
            acc[m4 * 4 + 0] += rv * s4.x;
            acc[m4 * 4 + 1] += rv * s4.y;
            acc[m4 * 4 + 2] += rv * s4.z;
            acc[m4 * 4 + 3] += rv * s4.w;
        }
    }
    float wbq = wpow[q];
    #pragma unroll
    for (int m = 0; m < 64; m++) acc[m] *= wbq;

    int jend = q | 31;
    for (int j = 0; j <= jend; j++) {
        float a = 0.f;
        const float4* krow = (const float4*)&ksm[j * 64];
        #pragma unroll
        for (int n4 = 0; n4 < 16; n4++) {
            float4 k4 = krow[n4];
            a += rrow[n4 * 4 + 0] * k4.x + rrow[n4 * 4 + 1] * k4.y
               + rrow[n4 * 4 + 2] * k4.z + rrow[n4 * 4 + 3] * k4.w;
        }
        float coef = (j < q) ? wpow[q - j - 1] : ((j == q) ? u : 0.0f);
        a *= coef;
        const float4* vrow = (const float4*)&vsm[j * 64];
        #pragma unroll
        for (int m4 = 0; m4 < 16; m4++) {
            float4 v4 = vrow[m4];
            acc[m4 * 4 + 0] += a * v4.x;
            acc[m4 * 4 + 1] += a * v4.y;
            acc[m4 * 4 + 2] += a * v4.z;
            acc[m4 * 4 + 3] += a * v4.w;
        }
    }

    float* yo = y + base + (size_t)q * CC;
    #pragma unroll
    for (int m4 = 0; m4 < 16; m4++) {
        float4 o4 = make_float4(acc[m4 * 4 + 0], acc[m4 * 4 + 1], acc[m4 * 4 + 2], acc[m4 * 4 + 3]);
        *(float4*)(yo + m4 * 4) = o4;
    }
}

// ---------------- GroupNorm * g ----------------
__global__ __launch_bounds__(256) void gn_mul_kernel(const float* __restrict__ y,
                                                     const float* __restrict__ gnw,
                                                     const float* __restrict__ gnb,
                                                     const float* __restrict__ g,
                                                     float* __restrict__ yg)
{
    int row = blockIdx.x;
    int tid = threadIdx.x;
    size_t off = (size_t)row * CC;
    float4 v = ((const float4*)(y + off))[tid];
    float s  = v.x + v.y + v.z + v.w;
    float sq = v.x*v.x + v.y*v.y + v.z*v.z + v.w*v.w;
    #pragma unroll
    for (int o = 8; o >= 1; o >>= 1) {
        s  += __shfl_xor_sync(0xffffffffu, s,  o);
        sq += __shfl_xor_sync(0xffffffffu, sq, o);
    }
    float mu   = s * (1.0f / 64.0f);
    float var  = sq * (1.0f / 64.0f) - mu * mu;
    float rstd = rsqrtf(var + EPS_GN);
    float4 ww = ((const float4*)gnw)[tid];
    float4 bb = ((const float4*)gnb)[tid];
    float4 gg = ((const float4*)(g + off))[tid];
    float4 o4;
    o4.x = ((v.x - mu) * rstd * ww.x + bb.x) * gg.x;
    o4.y = ((v.y - mu) * rstd * ww.y + bb.y) * gg.y;
    o4.z = ((v.z - mu) * rstd * ww.z + bb.z) * gg.z;
    o4.w = ((v.w - mu) * rstd * ww.w + bb.w) * gg.w;
    ((float4*)(yg + off))[tid] = o4;
}

// ---------------- host launcher ----------------
extern "C" void kernel_launch(void* const* d_in, const int* in_sizes, int n_in,
                              void* d_out, int out_size)
{
    const float* x      = (const float*)d_in[0];
    const float* ln1w   = (const float*)d_in[1];
    const float* ln1b   = (const float*)d_in[2];
    const float* maak   = (const float*)d_in[3];
    const float* maav   = (const float*)d_in[4];
    const float* maar   = (const float*)d_in[5];
    const float* maag   = (const float*)d_in[6];
    const float* decay  = (const float*)d_in[7];
    const float* faaaa  = (const float*)d_in[8];
    const float* Wr     = (const float*)d_in[9];
    const float* Wk     = (const float*)d_in[10];
    const float* Wv     = (const float*)d_in[11];
    const float* Wg     = (const float*)d_in[12];
    const float* Wo     = (const float*)d_in[13];
    const float* gnw    = (const float*)d_in[14];
    const float* gnb    = (const float*)d_in[15];
    const float* ln2w   = (const float*)d_in[16];
    const float* ln2b   = (const float*)d_in[17];
    const float* cmaak  = (const float*)d_in[18];
    const float* cmaar  = (const float*)d_in[19];
    const float* Wck    = (const float*)d_in[20];
    const float* Wcv    = (const float*)d_in[21];
    const float* Wcr    = (const float*)d_in[22];
    float* out = (float*)d_out;

    float* sc = nullptr;
    cudaGetSymbolAddress((void**)&sc, g_scratch);

    float* xln  = sc + OFF_XLN;
    float* xk   = sc + OFF_XK;
    float* xv   = sc + OFF_XV;
    float* xr   = sc + OFF_XR;
    float* xg   = sc + OFF_XG;
    float* rb   = sc + OFF_R;
    float* kb   = sc + OFF_K;
    float* vb   = sc + OFF_V;
    float* gb   = sc + OFF_G;
    float* yb   = sc + OFF_Y;
    float* ygb  = sc + OFF_YG;
    float* x1   = sc + OFF_X1;
    float* xln2 = sc + OFF_XLN2;
    float* xk2  = sc + OFF_XK2;
    float* xr2  = sc + OFF_XR2;
    float* hv   = sc + OFF_HV;
    float* hb   = sc + OFF_H;
    float* Sb   = sc + OFF_S;
    float* STb  = sc + OFF_ST;

    cudaFuncSetAttribute(wkv_y_kernel, cudaFuncAttributeMaxDynamicSharedMemorySize, WKV_Y_SMEM);
    cudaFuncSetAttribute(gemm_tc_kernel, cudaFuncAttributeMaxDynamicSharedMemorySize, (int)GEMM_SMEM);

    dim3 g1024(1024 / 128, MTOT / 128);   // (8,128)
    dim3 g3072(3072 / 128, MTOT / 128);   // (24,128)
    int mixBlocks = BTC / 4 / 256;

    // ---- time mix ----
    ln_kernel<<<MTOT, 256>>>(x, ln1w, ln1b, xln);
    tmix_mix_kernel<<<mixBlocks, 256>>>(xln, maak, maav, maar, maag, xk, xv, xr, xg);
    gemm_tc_kernel<<<g1024, 256, GEMM_SMEM>>>(xr, Wr, rb, 1024, 1024, 0, nullptr, nullptr);
    gemm_tc_kernel<<<g1024, 256, GEMM_SMEM>>>(xk, Wk, kb, 1024, 1024, 0, nullptr, nullptr);
    gemm_tc_kernel<<<g1024, 256, GEMM_SMEM>>>(xv, Wv, vb, 1024, 1024, 0, nullptr, nullptr);
    gemm_tc_kernel<<<g1024, 256, GEMM_SMEM>>>(xg, Wg, gb, 1024, 1024, 1, nullptr, nullptr);  // silu

    wkv_s_kernel<<<BB * HH * NCK, 256>>>(kb, vb, decay, Sb);
    wkv_scan_kernel<<<BB * HH, 256>>>(Sb, decay, STb);
    wkv_y_kernel<<<BB * HH * NCK, 256, WKV_Y_SMEM>>>(rb, kb, vb, STb, decay, faaaa, yb);

    gn_mul_kernel<<<MTOT, 256>>>(yb, gnw, gnb, gb, ygb);
    gemm_tc_kernel<<<g1024, 256, GEMM_SMEM>>>(ygb, Wo, x1, 1024, 1024, 4, x, nullptr);       // + residual

    // ---- channel mix ----
    ln_kernel<<<MTOT, 256>>>(x1, ln2w, ln2b, xln2);
    cmix_mix_kernel<<<mixBlocks, 256>>>(xln2, cmaak, cmaar, xk2, xr2);
    gemm_tc_kernel<<<g3072, 256, GEMM_SMEM>>>(xk2, Wck, hb, 3072, 1024, 2, nullptr, nullptr); // relu^2
    gemm_tc_kernel<<<g1024, 256, GEMM_SMEM>>>(hb, Wcv, hv, 1024, 3072, 0, nullptr, nullptr);
    gemm_tc_kernel<<<g1024, 256, GEMM_SMEM>>>(xr2, Wcr, out, 1024, 1024, 3, hv, x1);          // sigmoid*hv + x1
}

// round 4
// speedup vs baseline: 3.5733x; 1.2639x over previous
#include <cuda_runtime.h>
#include <math.h>
#include <stdint.h>

// ---------------- problem constants ----------------
#define BB 4
#define TT 4096
#define CC 1024
#define HH 16
#define NHD 64
#define QQ 256
#define NCK 16
#define MTOT (BB*TT)          // 16384
#define BTC (BB*TT*CC)        // 16777216
#define EPS_LN 1e-5f
#define EPS_GN (1e-5f*64.0f)

// ---------------- scratch ----------------
#define SCR_TOTAL (19ull*BTC + 8388608ull + 12582912ull)
__device__ float g_scratch[SCR_TOTAL];

#define OFF_XLN  (0ull*BTC)
#define OFF_XK   (1ull*BTC)
#define OFF_XV   (2ull*BTC)
#define OFF_XR   (3ull*BTC)
#define OFF_XG   (4ull*BTC)
#define OFF_R    (5ull*BTC)
#define OFF_K    (6ull*BTC)
#define OFF_V    (7ull*BTC)
#define OFF_G    (8ull*BTC)
#define OFF_Y    (9ull*BTC)
#define OFF_YG   (10ull*BTC)
#define OFF_X1   (11ull*BTC)
#define OFF_XLN2 (12ull*BTC)
#define OFF_XK2  (13ull*BTC)
#define OFF_XR2  (14ull*BTC)
#define OFF_HV   (15ull*BTC)
#define OFF_H    (16ull*BTC)
#define OFF_S    (19ull*BTC)
#define OFF_ST   (19ull*BTC + 4194304ull)
#define OFF_WT   (19ull*BTC + 8388608ull)
#define OFF_WR_R  (OFF_WT + 0ull)
#define OFF_WK_R  (OFF_WT + 1048576ull)
#define OFF_WV_R  (OFF_WT + 2097152ull)
#define OFF_WG_R  (OFF_WT + 3145728ull)
#define OFF_WO_R  (OFF_WT + 4194304ull)
#define OFF_WCR_R (OFF_WT + 5242880ull)
#define OFF_WCK_R (OFF_WT + 6291456ull)
#define OFF_WCV_R (OFF_WT + 9437184ull)

// ---------------- helpers ----------------
__device__ __forceinline__ float tf32_rna(float x) {
    uint32_t u;
    asm("cvt.rna.tf32.f32 %0, %1;" : "=r"(u) : "f"(x));
    return __uint_as_float(u);
}

__device__ __forceinline__ uint32_t smem_u32(const void* p) {
    uint32_t a;
    asm("{ .reg .u64 t; cvta.to.shared.u64 t, %1; cvt.u32.u64 %0, t; }" : "=r"(a) : "l"(p));
    return a;
}

__device__ __forceinline__ void cp16(uint32_t dst, const float* src) {
    asm volatile("cp.async.cg.shared.global [%0], [%1], 16;" :: "r"(dst), "l"(src) : "memory");
}
#define CP_COMMIT() asm volatile("cp.async.commit_group;" ::: "memory")
#define CP_WAIT_2() asm volatile("cp.async.wait_group 2;" ::: "memory")

// ---------------- weight tf32 pre-rounding ----------------
__global__ __launch_bounds__(256) void round_w_kernel(const float* __restrict__ src,
                                                      float* __restrict__ dst, int n4)
{
    int i = blockIdx.x * 256 + threadIdx.x;
    if (i < n4) {
        float4 v = ((const float4*)src)[i];
        v.x = tf32_rna(v.x); v.y = tf32_rna(v.y);
        v.z = tf32_rna(v.z); v.w = tf32_rna(v.w);
        ((float4*)dst)[i] = v;
    }
}

// ---------------- LayerNorm ----------------
__global__ __launch_bounds__(256) void ln_kernel(const float* __restrict__ x,
                                                 const float* __restrict__ w,
                                                 const float* __restrict__ b,
                                                 float* __restrict__ out)
{
    int row = blockIdx.x;
    int tid = threadIdx.x;
    const float4* xr = (const float4*)(x + (size_t)row * CC);
    float4 v = xr[tid];
    float s  = v.x + v.y + v.z + v.w;
    float sq = v.x*v.x + v.y*v.y + v.z*v.z + v.w*v.w;
    #pragma unroll
    for (int o = 16; o >= 1; o >>= 1) {
        s  += __shfl_xor_sync(0xffffffffu, s,  o);
        sq += __shfl_xor_sync(0xffffffffu, sq, o);
    }
    __shared__ float ss[8], ssq[8];
    int wid = tid >> 5, lane = tid & 31;
    if (lane == 0) { ss[wid] = s; ssq[wid] = sq; }
    __syncthreads();
    if (tid == 0) {
        float a = 0.f, c2 = 0.f;
        #pragma unroll
        for (int i = 0; i < 8; i++) { a += ss[i]; c2 += ssq[i]; }
        ss[0] = a; ssq[0] = c2;
    }
    __syncthreads();
    float mu   = ss[0] * (1.0f / CC);
    float var  = ssq[0] * (1.0f / CC) - mu * mu;
    float rstd = rsqrtf(var + EPS_LN);
    float4 ww = ((const float4*)w)[tid];
    float4 bb = ((const float4*)b)[tid];
    float4 o4;
    o4.x = (v.x - mu) * rstd * ww.x + bb.x;
    o4.y = (v.y - mu) * rstd * ww.y + bb.y;
    o4.z = (v.z - mu) * rstd * ww.z + bb.z;
    o4.w = (v.w - mu) * rstd * ww.w + bb.w;
    ((float4*)(out + (size_t)row * CC))[tid] = o4;
}

// ---------------- time-mix interpolation (tf32-rounded outputs: feed GEMMs) ----------------
__global__ __launch_bounds__(256) void tmix_mix_kernel(const float* __restrict__ xln,
                                                       const float* __restrict__ mk,
                                                       const float* __restrict__ mv,
                                                       const float* __restrict__ mr,
                                                       const float* __restrict__ mg,
                                                       float* __restrict__ xk,
                                                       float* __restrict__ xv,
                                                       float* __restrict__ xr,
                                                       float* __restrict__ xg)
{
    size_t i4 = (size_t)blockIdx.x * blockDim.x + threadIdx.x;
    int c4 = (int)(i4 % (CC / 4));
    size_t bt = i4 / (CC / 4);
    int t = (int)(bt % TT);
    float4 cur = ((const float4*)xln)[i4];
    float4 prev = make_float4(0.f, 0.f, 0.f, 0.f);
    if (t > 0) prev = ((const float4*)xln)[i4 - CC / 4];
    float4 xx = make_float4(prev.x - cur.x, prev.y - cur.y, prev.z - cur.z, prev.w - cur.w);
    float4 a, o;
    a = ((const float4*)mk)[c4];
    o.x = tf32_rna(cur.x + xx.x * a.x); o.y = tf32_rna(cur.y + xx.y * a.y);
    o.z = tf32_rna(cur.z + xx.z * a.z); o.w = tf32_rna(cur.w + xx.w * a.w);
    ((float4*)xk)[i4] = o;
    a = ((const float4*)mv)[c4];
    o.x = tf32_rna(cur.x + xx.x * a.x); o.y = tf32_rna(cur.y + xx.y * a.y);
    o.z = tf32_rna(cur.z + xx.z * a.z); o.w = tf32_rna(cur.w + xx.w * a.w);
    ((float4*)xv)[i4] = o;
    a = ((const float4*)mr)[c4];
    o.x = tf32_rna(cur.x + xx.x * a.x); o.y = tf32_rna(cur.y + xx.y * a.y);
    o.z = tf32_rna(cur.z + xx.z * a.z); o.w = tf32_rna(cur.w + xx.w * a.w);
    ((float4*)xr)[i4] = o;
    a = ((const float4*)mg)[c4];
    o.x = tf32_rna(cur.x + xx.x * a.x); o.y = tf32_rna(cur.y + xx.y * a.y);
    o.z = tf32_rna(cur.z + xx.z * a.z); o.w = tf32_rna(cur.w + xx.w * a.w);
    ((float4*)xg)[i4] = o;
}

// ---------------- channel-mix interpolation (tf32-rounded) ----------------
__global__ __launch_bounds__(256) void cmix_mix_kernel(const float* __restrict__ xln,
                                                       const float* __restrict__ mk,
                                                       const float* __restrict__ mr,
                                                       float* __restrict__ xk,
                                                       float* __restrict__ xr)
{
    size_t i4 = (size_t)blockIdx.x * blockDim.x + threadIdx.x;
    int c4 = (int)(i4 % (CC / 4));
    size_t bt = i4 / (CC / 4);
    int t = (int)(bt % TT);
    float4 cur = ((const float4*)xln)[i4];
    float4 prev = make_float4(0.f, 0.f, 0.f, 0.f);
    if (t > 0) prev = ((const float4*)xln)[i4 - CC / 4];
    float4 xx = make_float4(prev.x - cur.x, prev.y - cur.y, prev.z - cur.z, prev.w - cur.w);
    float4 a, o;
    a = ((const float4*)mk)[c4];
    o.x = tf32_rna(cur.x + xx.x * a.x); o.y = tf32_rna(cur.y + xx.y * a.y);
    o.z = tf32_rna(cur.z + xx.z * a.z); o.w = tf32_rna(cur.w + xx.w * a.w);
    ((float4*)xk)[i4] = o;
    a = ((const float4*)mr)[c4];
    o.x = tf32_rna(cur.x + xx.x * a.x); o.y = tf32_rna(cur.y + xx.y * a.y);
    o.z = tf32_rna(cur.z + xx.z * a.z); o.w = tf32_rna(cur.w + xx.w * a.w);
    ((float4*)xr)[i4] = o;
}

// ---------------- tf32 tensor-core GEMM (cp.async 3-stage pipeline) ----------------
// Cout[M,Nn] = A[M,K] @ W[Nn,K]^T + epilogue.
// 128x128 tiles, k-tile 32, 256 threads (8 warps = 2x4), warp tile 64x32 = 4x4 m16n8k8.
// Stage layout: A rows [0,128) then W rows [0,128), row stride 36 floats.
// Inputs are pre-rounded to tf32 (producers), so HMMA's internal truncation is exact.
// epi: 0 plain, 1 silu, 2 relu^2 (+tf32 round), 3 sigmoid()*aux1+aux2, 4 +aux1
#define STG_FLOATS 9216                       // 256 rows * 36 floats
#define GEMM_SMEM (3 * STG_FLOATS * 4)        // 110592 bytes

__device__ __forceinline__ void mma_tf32(float c[4],
                                         const uint32_t a[4],
                                         const uint32_t b[2])
{
    asm volatile(
        "mma.sync.aligned.m16n8k8.row.col.f32.tf32.tf32.f32 "
        "{%0,%1,%2,%3}, {%4,%5,%6,%7}, {%8,%9}, {%0,%1,%2,%3};\n"
        : "+f"(c[0]), "+f"(c[1]), "+f"(c[2]), "+f"(c[3])
        : "r"(a[0]), "r"(a[1]), "r"(a[2]), "r"(a[3]),
          "r"(b[0]), "r"(b[1]));
}

__device__ __forceinline__ float gemm_epi(float vv, int epi, const float* aux1,
                                          const float* aux2, size_t o)
{
    if (epi == 1) {
        vv = vv / (1.f + expf(-vv));
    } else if (epi == 2) {
        vv = fmaxf(vv, 0.f); vv = tf32_rna(vv * vv);
    } else if (epi == 3) {
        vv = 1.f / (1.f + expf(-vv));
        vv = vv * aux1[o] + aux2[o];
    } else if (epi == 4) {
        vv = vv + aux1[o];
    }
    return vv;
}

__global__ void __launch_bounds__(256, 2)
gemm_tc_kernel(const float* __restrict__ A, const float* __restrict__ W,
               float* __restrict__ Co, int Nn, int K, int epi,
               const float* __restrict__ aux1, const float* __restrict__ aux2)
{
    extern __shared__ float sm[];
    int tid = threadIdx.x;
    int n0 = blockIdx.x * 128;
    int m0 = blockIdx.y * 128;
    int wid = tid >> 5, lane = tid & 31;
    int wm = wid >> 2, wn = wid & 3;
    int gid = lane >> 2, tg = lane & 3;

    // per-thread async-copy indices: j = 16B chunk within row, r0 = base row
    int j  = tid & 7;            // chunk 0..7 (32 floats/row = 8 chunks)
    int r0 = tid >> 3;           // row 0..31 (+32*i)
    const float* pA = A + ((size_t)m0 + r0) * K + j * 4;
    const float* pW = W + ((size_t)n0 + r0) * K + j * 4;
    uint32_t smb = smem_u32(sm);
    uint32_t dstA = smb + (uint32_t)(r0 * 36 + j * 4) * 4u;
    uint32_t dstW = dstA + 4608u * 4u;

    float acc[4][4][4];
    #pragma unroll
    for (int mi = 0; mi < 4; mi++)
        #pragma unroll
        for (int ni = 0; ni < 4; ni++)
            #pragma unroll
            for (int e = 0; e < 4; e++) acc[mi][ni][e] = 0.f;

    int NC = K >> 5;

    // prologue: stages 0..2
    #pragma unroll
    for (int s = 0; s < 3; s++) {
        uint32_t so = (uint32_t)(s * STG_FLOATS) * 4u;
        int kf = s * 32;
        #pragma unroll
        for (int i = 0; i < 4; i++) {
            cp16(dstA + so + (uint32_t)(i * 32 * 36) * 4u, pA + (size_t)(i * 32) * K + kf);
            cp16(dstW + so + (uint32_t)(i * 32 * 36) * 4u, pW + (size_t)(i * 32) * K + kf);
        }
        CP_COMMIT();
    }

    // precomputed fragment smem row offsets (floats)
    int aoff[4], boff[4];
    #pragma unroll
    for (int mi = 0; mi < 4; mi++) aoff[mi] = (wm * 64 + mi * 16 + gid) * 36 + tg;
    #pragma unroll
    for (int ni = 0; ni < 4; ni++) boff[ni] = 4608 + (wn * 32 + ni * 8 + gid) * 36 + tg;

    for (int t = 0; t < NC; t++) {
        CP_WAIT_2();
        __syncthreads();
        const float* St = sm + (t % 3) * STG_FLOATS;

        #pragma unroll
        for (int kk = 0; kk < 4; kk++) {
            int ks = kk * 8;
            uint32_t af[4][4];
            uint32_t bf[4][2];
            #pragma unroll
            for (int mi = 0; mi < 4; mi++) {
                const float* ap = St + aoff[mi] + ks;
                af[mi][0] = __float_as_uint(ap[0]);
                af[mi][1] = __float_as_uint(ap[8 * 36]);
                af[mi][2] = __float_as_uint(ap[4]);
                af[mi][3] = __float_as_uint(ap[8 * 36 + 4]);
            }
            #pragma unroll
            for (int ni = 0; ni < 4; ni++) {
                const float* bp = St + boff[ni] + ks;
                bf[ni][0] = __float_as_uint(bp[0]);
                bf[ni][1] = __float_as_uint(bp[4]);
            }
            #pragma unroll
            for (int mi = 0; mi < 4; mi++)
                #pragma unroll
                for (int ni = 0; ni < 4; ni++)
                    mma_tf32(acc[mi][ni], af[mi], bf[ni]);
        }
        __syncthreads();

        int lc = t + 3;
        if (lc < NC) {
            uint32_t so = (uint32_t)((t % 3) * STG_FLOATS) * 4u;
            int kf = lc * 32;
            #pragma unroll
            for (int i = 0; i < 4; i++) {
                cp16(dstA + so + (uint32_t)(i * 32 * 36) * 4u, pA + (size_t)(i * 32) * K + kf);
                cp16(dstW + so + (uint32_t)(i * 32 * 36) * 4u, pW + (size_t)(i * 32) * K + kf);
            }
        }
        CP_COMMIT();
    }

    // epilogue
    #pragma unroll
    for (int mi = 0; mi < 4; mi++) {
        int row0 = m0 + wm * 64 + mi * 16 + gid;
        #pragma unroll
        for (int ni = 0; ni < 4; ni++) {
            int col0 = n0 + wn * 32 + ni * 8 + tg * 2;
            size_t o0 = (size_t)row0 * Nn + col0;
            size_t o1 = (size_t)(row0 + 8) * Nn + col0;
            float2 v0, v1;
            v0.x = gemm_epi(acc[mi][ni][0], epi, aux1, aux2, o0);
            v0.y = gemm_epi(acc[mi][ni][1], epi, aux1, aux2, o0 + 1);
            v1.x = gemm_epi(acc[mi][ni][2], epi, aux1, aux2, o1);
            v1.y = gemm_epi(acc[mi][ni][3], epi, aux1, aux2, o1 + 1);
            *(float2*)(Co + o0) = v0;
            *(float2*)(Co + o1) = v1;
        }
    }
}

// ---------------- WKV: per-chunk state contribution S = (k*wk) @ v ----------------
__global__ __launch_bounds__(256) void wkv_s_kernel(const float* __restrict__ k,
                                                    const float* __restrict__ v,
                                                    const float* __restrict__ decay,
                                                    float* __restrict__ S)
{
    int blk = blockIdx.x;
    int c = blk % NCK;
    int h = (blk / NCK) % HH;
    int b = blk / (NCK * HH);
    __shared__ float ksm[64][64];
    __shared__ float vsm[64][64];
    __shared__ float wpow[256];
    int tid = threadIdx.x;
    float ew = expf(decay[h]);
    wpow[tid] = expf(-ew * (float)tid);
    int n  = tid >> 2;
    int mg = (tid & 3) * 16;
    float acc[16];
    #pragma unroll
    for (int jj = 0; jj < 16; jj++) acc[jj] = 0.f;

    size_t base = ((size_t)b * TT + (size_t)c * QQ) * CC + (size_t)h * NHD;

    for (int qc = 0; qc < 4; qc++) {
        __syncthreads();
        for (int l = tid; l < 64 * 16; l += 256) {
            int qq = l >> 4;
            int f  = (l & 15) * 4;
            *(float4*)&ksm[qq][f] = *(const float4*)(k + base + (size_t)(qc * 64 + qq) * CC + f);
            *(float4*)&vsm[qq][f] = *(const float4*)(v + base + (size_t)(qc * 64 + qq) * CC + f);
        }
        __syncthreads();
        #pragma unroll 4
        for (int qq = 0; qq < 64; qq++) {
            float kw = ksm[qq][n] * wpow[255 - (qc * 64 + qq)];
            const float4* vr = (const float4*)&vsm[qq][mg];
            float4 v0 = vr[0], v1 = vr[1], v2 = vr[2], v3 = vr[3];
            acc[0]  += kw * v0.x; acc[1]  += kw * v0.y; acc[2]  += kw * v0.z; acc[3]  += kw * v0.w;
            acc[4]  += kw * v1.x; acc[5]  += kw * v1.y; acc[6]  += kw * v1.z; acc[7]  += kw * v1.w;
            acc[8]  += kw * v2.x; acc[9]  += kw * v2.y; acc[10] += kw * v2.z; acc[11] += kw * v2.w;
            acc[12] += kw * v3.x; acc[13] += kw * v3.y; acc[14] += kw * v3.z; acc[15] += kw * v3.w;
        }
    }
    float* Sp = S + (size_t)blk * 4096 + n * 64 + mg;
    #pragma unroll
    for (int jj = 0; jj < 16; jj++) Sp[jj] = acc[jj];
}

// ---------------- WKV: inter-chunk prefix scan ----------------
__global__ __launch_bounds__(256) void wkv_scan_kernel(const float* __restrict__ S,
                                                       const float* __restrict__ decay,
                                                       float* __restrict__ ST)
{
    int bh = blockIdx.x;
    int h = bh % HH;
    float ws = expf(-expf(decay[h]) * 256.0f);
    int tid = threadIdx.x;
    size_t b0 = (size_t)bh * NCK * 4096;
    for (int r = 0; r < 16; r++) {
        int e = tid + r * 256;
        float st = 0.f;
        #pragma unroll
        for (int c = 0; c < NCK; c++) {
            ST[b0 + (size_t)c * 4096 + e] = st;
            st = ws * st + S[b0 + (size_t)c * 4096 + e];
        }
    }
}

// ---------------- WKV: per-chunk output ----------------
#define WKV_Y_SMEM ((256*64*2 + 4096 + 256) * 4)
__global__ __launch_bounds__(256) void wkv_y_kernel(const float* __restrict__ r,
                                                    const float* __restrict__ k,
                                                    const float* __restrict__ v,
                                                    const float* __restrict__ ST,
                                                    const float* __restrict__ decay,
                                                    const float* __restrict__ faaaa,
                                                    float* __restrict__ y)
{
    extern __shared__ float sm[];
    float* ksm  = sm;
    float* vsm  = sm + 16384;
    float* ssm  = sm + 32768;
    float* wpow = sm + 36864;

    int blk = blockIdx.x;
    int c = blk % NCK;
    int h = (blk / NCK) % HH;
    int b = blk / (NCK * HH);
    int tid = threadIdx.x;

    float ew = expf(decay[h]);
    float u  = faaaa[h];
    wpow[tid] = expf(-ew * (float)tid);

    size_t base = ((size_t)b * TT + (size_t)c * QQ) * CC + (size_t)h * NHD;

    for (int l = tid; l < 256 * 16; l += 256) {
        int qq = l >> 4;
        int f  = (l & 15) * 4;
        *(float4*)&ksm[qq * 64 + f] = *(const float4*)(k + base + (size_t)qq * CC + f);
        *(float4*)&vsm[qq * 64 + f] = *(const float4*)(v + base + (size_t)qq * CC + f);
    }
    size_t sbase = (size_t)blk * 4096;
    for (int l = tid; l < 1024; l += 256)
        *(float4*)&ssm[l * 4] = *(const float4*)(ST + sbase + (size_t)l * 4);
    __syncthreads();

    int q = tid;
    float rrow[64];
    {
        const float4* rg = (const float4*)(r + base + (size_t)q * CC);
        #pragma unroll
        for (int f = 0; f < 16; f++) {
            float4 t4 = rg[f];
            rrow[f * 4 + 0] = t4.x; rrow[f * 4 + 1] = t4.y;
            rrow[f * 4 + 2] = t4.z; rrow[f * 4 + 3] = t4.w;
        }
    }
    float acc[64];
    #pragma unroll
    for (int m = 0; m < 64; m++) acc[m] = 0.f;

    #pragma unroll 8
    for (int n = 0; n < 64; n++) {
        float rv = rrow[n];
        const float4* srow = (const float4*)&ssm[n * 64];
        #pragma unroll
        for (int m4 = 0; m4 < 16; m4++) {
            float4 s4 = srow[m4];
            acc[m4 * 4 + 0] += rv * s4.x;
            acc[m4 * 4 + 1] += rv * s4.y;
            acc[m4 * 4 + 2] += rv * s4.z;
            acc[m4 * 4 + 3] += rv * s4.w;
        }
    }
    float wbq = wpow[q];
    #pragma unroll
    for (int m = 0; m < 64; m++) acc[m] *= wbq;

    int jend = q | 31;
    for (int j = 0; j <= jend; j++) {
        float a = 0.f;
        const float4* krow = (const float4*)&ksm[j * 64];
        #pragma unroll
        for (int n4 = 0; n4 < 16; n4++) {
            float4 k4 = krow[n4];
            a += rrow[n4 * 4 + 0] * k4.x + rrow[n4 * 4 + 1] * k4.y
               + rrow[n4 * 4 + 2] * k4.z + rrow[n4 * 4 + 3] * k4.w;
        }
        float coef = (j < q) ? wpow[q - j - 1] : ((j == q) ? u : 0.0f);
        a *= coef;
        const float4* vrow = (const float4*)&vsm[j * 64];
        #pragma unroll
        for (int m4 = 0; m4 < 16; m4++) {
            float4 v4 = vrow[m4];
            acc[m4 * 4 + 0] += a * v4.x;
            acc[m4 * 4 + 1] += a * v4.y;
            acc[m4 * 4 + 2] += a * v4.z;
            acc[m4 * 4 + 3] += a * v4.w;
        }
    }

    float* yo = y + base + (size_t)q * CC;
    #pragma unroll
    for (int m4 = 0; m4 < 16; m4++) {
        float4 o4 = make_float4(acc[m4 * 4 + 0], acc[m4 * 4 + 1], acc[m4 * 4 + 2], acc[m4 * 4 + 3]);
        *(float4*)(yo + m4 * 4) = o4;
    }
}

// ---------------- GroupNorm * g (tf32-rounded output: feeds Wo GEMM) ----------------
__global__ __launch_bounds__(256) void gn_mul_kernel(const float* __restrict__ y,
                                                     const float* __restrict__ gnw,
                                                     const float* __restrict__ gnb,
                                                     const float* __restrict__ g,
                                                     float* __restrict__ yg)
{
    int row = blockIdx.x;
    int tid = threadIdx.x;
    size_t off = (size_t)row * CC;
    float4 v = ((const float4*)(y + off))[tid];
    float s  = v.x + v.y + v.z + v.w;
    float sq = v.x*v.x + v.y*v.y + v.z*v.z + v.w*v.w;
    #pragma unroll
    for (int o = 8; o >= 1; o >>= 1) {
        s  += __shfl_xor_sync(0xffffffffu, s,  o);
        sq += __shfl_xor_sync(0xffffffffu, sq, o);
    }
    float mu   = s * (1.0f / 64.0f);
    float var  = sq * (1.0f / 64.0f) - mu * mu;
    float rstd = rsqrtf(var + EPS_GN);
    float4 ww = ((const float4*)gnw)[tid];
    float4 bb = ((const float4*)gnb)[tid];
    float4 gg = ((const float4*)(g + off))[tid];
    float4 o4;
    o4.x = tf32_rna(((v.x - mu) * rstd * ww.x + bb.x) * gg.x);
    o4.y = tf32_rna(((v.y - mu) * rstd * ww.y + bb.y) * gg.y);
    o4.z = tf32_rna(((v.z - mu) * rstd * ww.z + bb.z) * gg.z);
    o4.w = tf32_rna(((v.w - mu) * rstd * ww.w + bb.w) * gg.w);
    ((float4*)(yg + off))[tid] = o4;
}

// ---------------- host launcher ----------------
extern "C" void kernel_launch(void* const* d_in, const int* in_sizes, int n_in,
                              void* d_out, int out_size)
{
    const float* x      = (const float*)d_in[0];
    const float* ln1w   = (const float*)d_in[1];
    const float* ln1b   = (const float*)d_in[2];
    const float* maak   = (const float*)d_in[3];
    const float* maav   = (const float*)d_in[4];
    const float* maar   = (const float*)d_in[5];
    const float* maag   = (const float*)d_in[6];
    const float* decay  = (const float*)d_in[7];
    const float* faaaa  = (const float*)d_in[8];
    const float* Wr     = (const float*)d_in[9];
    const float* Wk     = (const float*)d_in[10];
    const float* Wv     = (const float*)d_in[11];
    const float* Wg     = (const float*)d_in[12];
    const float* Wo     = (const float*)d_in[13];
    const float* gnw    = (const float*)d_in[14];
    const float* gnb    = (const float*)d_in[15];
    const float* ln2w   = (const float*)d_in[16];
    const float* ln2b   = (const float*)d_in[17];
    const float* cmaak  = (const float*)d_in[18];
    const float* cmaar  = (const float*)d_in[19];
    const float* Wck    = (const float*)d_in[20];
    const float* Wcv    = (const float*)d_in[21];
    const float* Wcr    = (const float*)d_in[22];
    float* out = (float*)d_out;

    float* sc = nullptr;
    cudaGetSymbolAddress((void**)&sc, g_scratch);

    float* xln  = sc + OFF_XLN;
    float* xk   = sc + OFF_XK;
    float* xv   = sc + OFF_XV;
    float* xr   = sc + OFF_XR;
    float* xg   = sc + OFF_XG;
    float* rb   = sc + OFF_R;
    float* kb   = sc + OFF_K;
    float* vb   = sc + OFF_V;
    float* gb   = sc + OFF_G;
    float* yb   = sc + OFF_Y;
    float* ygb  = sc + OFF_YG;
    float* x1   = sc + OFF_X1;
    float* xln2 = sc + OFF_XLN2;
    float* xk2  = sc + OFF_XK2;
    float* xr2  = sc + OFF_XR2;
    float* hv   = sc + OFF_HV;
    float* hb   = sc + OFF_H;
    float* Sb   = sc + OFF_S;
    float* STb  = sc + OFF_ST;
    float* WrR  = sc + OFF_WR_R;
    float* WkR  = sc + OFF_WK_R;
    float* WvR  = sc + OFF_WV_R;
    float* WgR  = sc + OFF_WG_R;
    float* WoR  = sc + OFF_WO_R;
    float* WcrR = sc + OFF_WCR_R;
    float* WckR = sc + OFF_WCK_R;
    float* WcvR = sc + OFF_WCV_R;

    cudaFuncSetAttribute(wkv_y_kernel, cudaFuncAttributeMaxDynamicSharedMemorySize, WKV_Y_SMEM);
    cudaFuncSetAttribute(gemm_tc_kernel, cudaFuncAttributeMaxDynamicSharedMemorySize, GEMM_SMEM);

    dim3 g1024(1024 / 128, MTOT / 128);   // (8, 128)
    dim3 g3072(3072 / 128, MTOT / 128);   // (24, 128)
    int mixBlocks = BTC / 4 / 256;
    int n4_1M = (CC * CC) / 4;
    int n4_3M = (3 * CC * CC) / 4;

    // ---- weight tf32 pre-rounding ----
    round_w_kernel<<<n4_1M / 256, 256>>>(Wr,  WrR,  n4_1M);
    round_w_kernel<<<n4_1M / 256, 256>>>(Wk,  WkR,  n4_1M);
    round_w_kernel<<<n4_1M / 256, 256>>>(Wv,  WvR,  n4_1M);
    round_w_kernel<<<n4_1M / 256, 256>>>(Wg,  WgR,  n4_1M);
    round_w_kernel<<<n4_1M / 256, 256>>>(Wo,  WoR,  n4_1M);
    round_w_kernel<<<n4_1M / 256, 256>>>(Wcr, WcrR, n4_1M);
    round_w_kernel<<<n4_3M / 256, 256>>>(Wck, WckR, n4_3M);
    round_w_kernel<<<n4_3M / 256, 256>>>(Wcv, WcvR, n4_3M);

    // ---- time mix ----
    ln_kernel<<<MTOT, 256>>>(x, ln1w, ln1b, xln);
    tmix_mix_kernel<<<mixBlocks, 256>>>(xln, maak, maav, maar, maag, xk, xv, xr, xg);
    gemm_tc_kernel<<<g1024, 256, GEMM_SMEM>>>(xr, WrR, rb, 1024, 1024, 0, nullptr, nullptr);
    gemm_tc_kernel<<<g1024, 256, GEMM_SMEM>>>(xk, WkR, kb, 1024, 1024, 0, nullptr, nullptr);
    gemm_tc_kernel<<<g1024, 256, GEMM_SMEM>>>(xv, WvR, vb, 1024, 1024, 0, nullptr, nullptr);
    gemm_tc_kernel<<<g1024, 256, GEMM_SMEM>>>(xg, WgR, gb, 1024, 1024, 1, nullptr, nullptr);  // silu

    wkv_s_kernel<<<BB * HH * NCK, 256>>>(kb, vb, decay, Sb);
    wkv_scan_kernel<<<BB * HH, 256>>>(Sb, decay, STb);
    wkv_y_kernel<<<BB * HH * NCK, 256, WKV_Y_SMEM>>>(rb, kb, vb, STb, decay, faaaa, yb);

    gn_mul_kernel<<<MTOT, 256>>>(yb, gnw, gnb, gb, ygb);
    gemm_tc_kernel<<<g1024, 256, GEMM_SMEM>>>(ygb, WoR, x1, 1024, 1024, 4, x, nullptr);       // + residual

    // ---- channel mix ----
    ln_kernel<<<MTOT, 256>>>(x1, ln2w, ln2b, xln2);
    cmix_mix_kernel<<<mixBlocks, 256>>>(xln2, cmaak, cmaar, xk2, xr2);
    gemm_tc_kernel<<<g3072, 256, GEMM_SMEM>>>(xk2, WckR, hb, 3072, 1024, 2, nullptr, nullptr); // relu^2
    gemm_tc_kernel<<<g1024, 256, GEMM_SMEM>>>(hb, WcvR, hv, 1024, 3072, 0, nullptr, nullptr);
    gemm_tc_kernel<<<g1024, 256, GEMM_SMEM>>>(xr2, WcrR, out, 1024, 1024, 3, hv, x1);          // sigmoid*hv + x1
}

// round 5
// speedup vs baseline: 3.7979x; 1.0629x over previous
#include <cuda_runtime.h>
#include <math.h>
#include <stdint.h>

// ---------------- problem constants ----------------
#define BB 4
#define TT 4096
#define CC 1024
#define HH 16
#define NHD 64
#define QQ 256
#define NCK 16
#define MTOT (BB*TT)          // 16384
#define BTC (BB*TT*CC)        // 16777216
#define EPS_LN 1e-5f
#define EPS_GN (1e-5f*64.0f)

// ---------------- scratch ----------------
#define SCR_TOTAL (19ull*BTC + 8388608ull + 12582912ull)
__device__ float g_scratch[SCR_TOTAL];

#define OFF_XK   (1ull*BTC)
#define OFF_XV   (2ull*BTC)
#define OFF_XR   (3ull*BTC)
#define OFF_XG   (4ull*BTC)
#define OFF_R    (5ull*BTC)
#define OFF_K    (6ull*BTC)
#define OFF_V    (7ull*BTC)
#define OFF_G    (8ull*BTC)
#define OFF_Y    (9ull*BTC)
#define OFF_YG   (10ull*BTC)
#define OFF_X1   (11ull*BTC)
#define OFF_XK2  (13ull*BTC)
#define OFF_XR2  (14ull*BTC)
#define OFF_HV   (15ull*BTC)
#define OFF_H    (16ull*BTC)
#define OFF_S    (19ull*BTC)
#define OFF_ST   (19ull*BTC + 4194304ull)
#define OFF_WT   (19ull*BTC + 8388608ull)
#define OFF_WR_R  (OFF_WT + 0ull)
#define OFF_WK_R  (OFF_WT + 1048576ull)
#define OFF_WV_R  (OFF_WT + 2097152ull)
#define OFF_WG_R  (OFF_WT + 3145728ull)
#define OFF_WO_R  (OFF_WT + 4194304ull)
#define OFF_WCR_R (OFF_WT + 5242880ull)
#define OFF_WCK_R (OFF_WT + 6291456ull)
#define OFF_WCV_R (OFF_WT + 9437184ull)

// ---------------- helpers ----------------
__device__ __forceinline__ float tf32_rna(float x) {
    uint32_t u;
    asm("cvt.rna.tf32.f32 %0, %1;" : "=r"(u) : "f"(x));
    return __uint_as_float(u);
}

__device__ __forceinline__ uint32_t smem_u32(const void* p) {
    uint32_t a;
    asm("{ .reg .u64 t; cvta.to.shared.u64 t, %1; cvt.u32.u64 %0, t; }" : "=r"(a) : "l"(p));
    return a;
}

__device__ __forceinline__ void cp16(uint32_t dst, const float* src) {
    asm volatile("cp.async.cg.shared.global [%0], [%1], 16;" :: "r"(dst), "l"(src) : "memory");
}
#define CP_COMMIT() asm volatile("cp.async.commit_group;" ::: "memory")
#define CP_WAIT_1() asm volatile("cp.async.wait_group 1;" ::: "memory")

// ---------------- weight tf32 pre-rounding ----------------
__global__ __launch_bounds__(256) void round_w_kernel(const float* __restrict__ src,
                                                      float* __restrict__ dst, int n4)
{
    int i = blockIdx.x * 256 + threadIdx.x;
    if (i < n4) {
        float4 v = ((const float4*)src)[i];
        v.x = tf32_rna(v.x); v.y = tf32_rna(v.y);
        v.z = tf32_rna(v.z); v.w = tf32_rna(v.w);
        ((float4*)dst)[i] = v;
    }
}

// ---------------- fused LayerNorm + time-shift mix ----------------
// One block per (b,t) row. Loads row t and row t-1, computes both LN in-block,
// emits the 4 mixed tensors (tf32-rounded). t==0: shifted row is all-zero.
template<int NOUT>
__global__ __launch_bounds__(256) void ln_mix_kernel(const float* __restrict__ x,
                                                     const float* __restrict__ w,
                                                     const float* __restrict__ b,
                                                     const float* __restrict__ m0,
                                                     const float* __restrict__ m1,
                                                     const float* __restrict__ m2,
                                                     const float* __restrict__ m3,
                                                     float* __restrict__ o0,
                                                     float* __restrict__ o1,
                                                     float* __restrict__ o2,
                                                     float* __restrict__ o3)
{
    int row = blockIdx.x;
    int t = row % TT;
    int tid = threadIdx.x;
    size_t off = (size_t)row * CC;
    float4 cur = ((const float4*)(x + off))[tid];
    float4 prv = make_float4(0.f, 0.f, 0.f, 0.f);
    if (t > 0) prv = ((const float4*)(x + off - CC))[tid];

    float s0 = cur.x + cur.y + cur.z + cur.w;
    float q0 = cur.x*cur.x + cur.y*cur.y + cur.z*cur.z + cur.w*cur.w;
    float s1 = prv.x + prv.y + prv.z + prv.w;
    float q1 = prv.x*prv.x + prv.y*prv.y + prv.z*prv.z + prv.w*prv.w;
    #pragma unroll
    for (int o = 16; o >= 1; o >>= 1) {
        s0 += __shfl_xor_sync(0xffffffffu, s0, o);
        q0 += __shfl_xor_sync(0xffffffffu, q0, o);
        s1 += __shfl_xor_sync(0xffffffffu, s1, o);
        q1 += __shfl_xor_sync(0xffffffffu, q1, o);
    }
    __shared__ float red[4][8];
    int wid = tid >> 5, lane = tid & 31;
    if (lane == 0) { red[0][wid] = s0; red[1][wid] = q0; red[2][wid] = s1; red[3][wid] = q1; }
    __syncthreads();
    if (tid == 0) {
        float a0 = 0, a1 = 0, a2 = 0, a3 = 0;
        #pragma unroll
        for (int i = 0; i < 8; i++) { a0 += red[0][i]; a1 += red[1][i]; a2 += red[2][i]; a3 += red[3][i]; }
        red[0][0] = a0; red[1][0] = a1; red[2][0] = a2; red[3][0] = a3;
    }
    __syncthreads();
    float mu0 = red[0][0] * (1.0f / CC);
    float rs0 = rsqrtf(red[1][0] * (1.0f / CC) - mu0 * mu0 + EPS_LN);
    float mu1 = red[2][0] * (1.0f / CC);
    float rs1 = rsqrtf(red[3][0] * (1.0f / CC) - mu1 * mu1 + EPS_LN);

    float4 ww = ((const float4*)w)[tid];
    float4 bb = ((const float4*)b)[tid];
    float4 lc, lp;
    lc.x = (cur.x - mu0) * rs0 * ww.x + bb.x;
    lc.y = (cur.y - mu0) * rs0 * ww.y + bb.y;
    lc.z = (cur.z - mu0) * rs0 * ww.z + bb.z;
    lc.w = (cur.w - mu0) * rs0 * ww.w + bb.w;
    if (t > 0) {
        lp.x = (prv.x - mu1) * rs1 * ww.x + bb.x;
        lp.y = (prv.y - mu1) * rs1 * ww.y + bb.y;
        lp.z = (prv.z - mu1) * rs1 * ww.z + bb.z;
        lp.w = (prv.w - mu1) * rs1 * ww.w + bb.w;
    } else {
        lp = make_float4(0.f, 0.f, 0.f, 0.f);
    }
    float4 xx = make_float4(lp.x - lc.x, lp.y - lc.y, lp.z - lc.z, lp.w - lc.w);

    float4 a, o;
    a = ((const float4*)m0)[tid];
    o.x = tf32_rna(lc.x + xx.x * a.x); o.y = tf32_rna(lc.y + xx.y * a.y);
    o.z = tf32_rna(lc.z + xx.z * a.z); o.w = tf32_rna(lc.w + xx.w * a.w);
    ((float4*)(o0 + off))[tid] = o;
    a = ((const float4*)m1)[tid];
    o.x = tf32_rna(lc.x + xx.x * a.x); o.y = tf32_rna(lc.y + xx.y * a.y);
    o.z = tf32_rna(lc.z + xx.z * a.z); o.w = tf32_rna(lc.w + xx.w * a.w);
    ((float4*)(o1 + off))[tid] = o;
    if (NOUT == 4) {
        a = ((const float4*)m2)[tid];
        o.x = tf32_rna(lc.x + xx.x * a.x); o.y = tf32_rna(lc.y + xx.y * a.y);
        o.z = tf32_rna(lc.z + xx.z * a.z); o.w = tf32_rna(lc.w + xx.w * a.w);
        ((float4*)(o2 + off))[tid] = o;
        a = ((const float4*)m3)[tid];
        o.x = tf32_rna(lc.x + xx.x * a.x); o.y = tf32_rna(lc.y + xx.y * a.y);
        o.z = tf32_rna(lc.z + xx.z * a.z); o.w = tf32_rna(lc.w + xx.w * a.w);
        ((float4*)(o3 + off))[tid] = o;
    }
}

// ---------------- tf32 tensor-core GEMM (cp.async 2-stage, 2 CTAs/SM) ----------------
// Cout[M,Nn] = A[M,K] @ W[Nn,K]^T + epilogue.
// 128x128 tiles, k-tile 32, 256 threads (8 warps = 2x4), warp tile 64x32 = 4x4 m16n8k8.
// epi: 0 plain, 1 silu, 2 relu^2 (+tf32 round), 3 sigmoid()*aux1+aux2, 4 +aux1
#define STG_FLOATS 9216                       // 256 rows * 36 floats
#define GEMM_SMEM (2 * STG_FLOATS * 4)        // 73728 bytes

__device__ __forceinline__ void mma_tf32(float c[4],
                                         const uint32_t a[4],
                                         const uint32_t b[2])
{
    asm volatile(
        "mma.sync.aligned.m16n8k8.row.col.f32.tf32.tf32.f32 "
        "{%0,%1,%2,%3}, {%4,%5,%6,%7}, {%8,%9}, {%0,%1,%2,%3};\n"
        : "+f"(c[0]), "+f"(c[1]), "+f"(c[2]), "+f"(c[3])
        : "r"(a[0]), "r"(a[1]), "r"(a[2]), "r"(a[3]),
          "r"(b[0]), "r"(b[1]));
}

__device__ __forceinline__ float gemm_epi(float vv, int epi, const float* aux1,
                                          const float* aux2, size_t o)
{
    if (epi == 1) {
        vv = vv / (1.f + expf(-vv));
    } else if (epi == 2) {
        vv = fmaxf(vv, 0.f); vv = tf32_rna(vv * vv);
    } else if (epi == 3) {
        vv = 1.f / (1.f + expf(-vv));
        vv = vv * aux1[o] + aux2[o];
    } else if (epi == 4) {
        vv = vv + aux1[o];
    }
    return vv;
}

__global__ void __launch_bounds__(256, 2)
gemm_tc_kernel(const float* __restrict__ A, const float* __restrict__ W,
               float* __restrict__ Co, int Nn, int K, int epi,
               const float* __restrict__ aux1, const float* __restrict__ aux2)
{
    extern __shared__ float sm[];
    int tid = threadIdx.x;
    int n0 = blockIdx.x * 128;
    int m0 = blockIdx.y * 128;
    int wid = tid >> 5, lane = tid & 31;
    int wm = wid >> 2, wn = wid & 3;
    int gid = lane >> 2, tg = lane & 3;

    int j  = tid & 7;
    int r0 = tid >> 3;
    const float* pA = A + ((size_t)m0 + r0) * K + j * 4;
    const float* pW = W + ((size_t)n0 + r0) * K + j * 4;
    uint32_t smb = smem_u32(sm);
    uint32_t dstA = smb + (uint32_t)(r0 * 36 + j * 4) * 4u;
    uint32_t dstW = dstA + 4608u * 4u;

    float acc[4][4][4];
    #pragma unroll
    for (int mi = 0; mi < 4; mi++)
        #pragma unroll
        for (int ni = 0; ni < 4; ni++)
            #pragma unroll
            for (int e = 0; e < 4; e++) acc[mi][ni][e] = 0.f;

    int NC = K >> 5;

    // prologue: stages 0,1
    #pragma unroll
    for (int s = 0; s < 2; s++) {
        uint32_t so = (uint32_t)(s * STG_FLOATS) * 4u;
        int kf = s * 32;
        #pragma unroll
        for (int i = 0; i < 4; i++) {
            cp16(dstA + so + (uint32_t)(i * 32 * 36) * 4u, pA + (size_t)(i * 32) * K + kf);
            cp16(dstW + so + (uint32_t)(i * 32 * 36) * 4u, pW + (size_t)(i * 32) * K + kf);
        }
        CP_COMMIT();
    }

    int aoff[4], boff[4];
    #pragma unroll
    for (int mi = 0; mi < 4; mi++) aoff[mi] = (wm * 64 + mi * 16 + gid) * 36 + tg;
    #pragma unroll
    for (int ni = 0; ni < 4; ni++) boff[ni] = 4608 + (wn * 32 + ni * 8 + gid) * 36 + tg;

    for (int t = 0; t < NC; t++) {
        CP_WAIT_1();
        __syncthreads();
        const float* St = sm + (t & 1) * STG_FLOATS;

        #pragma unroll
        for (int kk = 0; kk < 4; kk++) {
            int ks = kk * 8;
            uint32_t af[4][4];
            uint32_t bf[4][2];
            #pragma unroll
            for (int mi = 0; mi < 4; mi++) {
                const float* ap = St + aoff[mi] + ks;
                af[mi][0] = __float_as_uint(ap[0]);
                af[mi][1] = __float_as_uint(ap[8 * 36]);
                af[mi][2] = __float_as_uint(ap[4]);
                af[mi][3] = __float_as_uint(ap[8 * 36 + 4]);
            }
            #pragma unroll
            for (int ni = 0; ni < 4; ni++) {
                const float* bp = St + boff[ni] + ks;
                bf[ni][0] = __float_as_uint(bp[0]);
                bf[ni][1] = __float_as_uint(bp[4]);
            }
            #pragma unroll
            for (int mi = 0; mi < 4; mi++)
                #pragma unroll
                for (int ni = 0; ni < 4; ni++)
                    mma_tf32(acc[mi][ni], af[mi], bf[ni]);
        }
        __syncthreads();

        int lc = t + 2;
        if (lc < NC) {
            uint32_t so = (uint32_t)((t & 1) * STG_FLOATS) * 4u;
            int kf = lc * 32;
            #pragma unroll
            for (int i = 0; i < 4; i++) {
                cp16(dstA + so + (uint32_t)(i * 32 * 36) * 4u, pA + (size_t)(i * 32) * K + kf);
                cp16(dstW + so + (uint32_t)(i * 32 * 36) * 4u, pW + (size_t)(i * 32) * K + kf);
            }
        }
        CP_COMMIT();
    }

    // epilogue
    #pragma unroll
    for (int mi = 0; mi < 4; mi++) {
        int row0 = m0 + wm * 64 + mi * 16 + gid;
        #pragma unroll
        for (int ni = 0; ni < 4; ni++) {
            int col0 = n0 + wn * 32 + ni * 8 + tg * 2;
            size_t o0 = (size_t)row0 * Nn + col0;
            size_t o1 = (size_t)(row0 + 8) * Nn + col0;
            float2 v0, v1;
            v0.x = gemm_epi(acc[mi][ni][0], epi, aux1, aux2, o0);
            v0.y = gemm_epi(acc[mi][ni][1], epi, aux1, aux2, o0 + 1);
            v1.x = gemm_epi(acc[mi][ni][2], epi, aux1, aux2, o1);
            v1.y = gemm_epi(acc[mi][ni][3], epi, aux1, aux2, o1 + 1);
            *(float2*)(Co + o0) = v0;
            *(float2*)(Co + o1) = v1;
        }
    }
}

// ---------------- WKV: per-chunk state contribution S = (k*wk) @ v ----------------
__global__ __launch_bounds__(256) void wkv_s_kernel(const float* __restrict__ k,
                                                    const float* __restrict__ v,
                                                    const float* __restrict__ decay,
                                                    float* __restrict__ S)
{
    int blk = blockIdx.x;
    int c = blk % NCK;
    int h = (blk / NCK) % HH;
    int b = blk / (NCK * HH);
    __shared__ float ksm[64][64];
    __shared__ float vsm[64][64];
    __shared__ float wpow[256];
    int tid = threadIdx.x;
    float ew = expf(decay[h]);
    wpow[tid] = expf(-ew * (float)tid);
    int n  = tid >> 2;
    int mg = (tid & 3) * 16;
    float acc[16];
    #pragma unroll
    for (int jj = 0; jj < 16; jj++) acc[jj] = 0.f;

    size_t base = ((size_t)b * TT + (size_t)c * QQ) * CC + (size_t)h * NHD;

    for (int qc = 0; qc < 4; qc++) {
        __syncthreads();
        for (int l = tid; l < 64 * 16; l += 256) {
            int qq = l >> 4;
            int f  = (l & 15) * 4;
            *(float4*)&ksm[qq][f] = *(const float4*)(k + base + (size_t)(qc * 64 + qq) * CC + f);
            *(float4*)&vsm[qq][f] = *(const float4*)(v + base + (size_t)(qc * 64 + qq) * CC + f);
        }
        __syncthreads();
        #pragma unroll 4
        for (int qq = 0; qq < 64; qq++) {
            float kw = ksm[qq][n] * wpow[255 - (qc * 64 + qq)];
            const float4* vr = (const float4*)&vsm[qq][mg];
            float4 v0 = vr[0], v1 = vr[1], v2 = vr[2], v3 = vr[3];
            acc[0]  += kw * v0.x; acc[1]  += kw * v0.y; acc[2]  += kw * v0.z; acc[3]  += kw * v0.w;
            acc[4]  += kw * v1.x; acc[5]  += kw * v1.y; acc[6]  += kw * v1.z; acc[7]  += kw * v1.w;
            acc[8]  += kw * v2.x; acc[9]  += kw * v2.y; acc[10] += kw * v2.z; acc[11] += kw * v2.w;
            acc[12] += kw * v3.x; acc[13] += kw * v3.y; acc[14] += kw * v3.z; acc[15] += kw * v3.w;
        }
    }
    float* Sp = S + (size_t)blk * 4096 + n * 64 + mg;
    #pragma unroll
    for (int jj = 0; jj < 16; jj++) Sp[jj] = acc[jj];
}

// ---------------- WKV: inter-chunk prefix scan ----------------
__global__ __launch_bounds__(256) void wkv_scan_kernel(const float* __restrict__ S,
                                                       const float* __restrict__ decay,
                                                       float* __restrict__ ST)
{
    int bh = blockIdx.x;
    int h = bh % HH;
    float ws = expf(-expf(decay[h]) * 256.0f);
    int tid = threadIdx.x;
    size_t b0 = (size_t)bh * NCK * 4096;
    for (int r = 0; r < 16; r++) {
        int e = tid + r * 256;
        float st = 0.f;
        #pragma unroll
        for (int c = 0; c < NCK; c++) {
            ST[b0 + (size_t)c * 4096 + e] = st;
            st = ws * st + S[b0 + (size_t)c * 4096 + e];
        }
    }
}

// ---------------- WKV: per-chunk output ----------------
#define WKV_Y_SMEM ((256*64*2 + 4096 + 256) * 4)
__global__ __launch_bounds__(256) void wkv_y_kernel(const float* __restrict__ r,
                                                    const float* __restrict__ k,
                                                    const float* __restrict__ v,
                                                    const float* __restrict__ ST,
                                                    const float* __restrict__ decay,
                                                    const float* __restrict__ faaaa,
                                                    float* __restrict__ y)
{
    extern __shared__ float sm[];
    float* ksm  = sm;
    float* vsm  = sm + 16384;
    float* ssm  = sm + 32768;
    float* wpow = sm + 36864;

    int blk = blockIdx.x;
    int c = blk % NCK;
    int h = (blk / NCK) % HH;
    int b = blk / (NCK * HH);
    int tid = threadIdx.x;

    float ew = expf(decay[h]);
    float u  = faaaa[h];
    wpow[tid] = expf(-ew * (float)tid);

    size_t base = ((size_t)b * TT + (size_t)c * QQ) * CC + (size_t)h * NHD;

    for (int l = tid; l < 256 * 16; l += 256) {
        int qq = l >> 4;
        int f  = (l & 15) * 4;
        *(float4*)&ksm[qq * 64 + f] = *(const float4*)(k + base + (size_t)qq * CC + f);
        *(float4*)&vsm[qq * 64 + f] = *(const float4*)(v + base + (size_t)qq * CC + f);
    }
    size_t sbase = (size_t)blk * 4096;
    for (int l = tid; l < 1024; l += 256)
        *(float4*)&ssm[l * 4] = *(const float4*)(ST + sbase + (size_t)l * 4);
    __syncthreads();

    int q = tid;
    float rrow[64];
    {
        const float4* rg = (const float4*)(r + base + (size_t)q * CC);
        #pragma unroll
        for (int f = 0; f < 16; f++) {
            float4 t4 = rg[f];
            rrow[f * 4 + 0] = t4.x; rrow[f * 4 + 1] = t4.y;
            rrow[f * 4 + 2] = t4.z; rrow[f * 4 + 3] = t4.w;
        }
    }
    float acc[64];
    #pragma unroll
    for (int m = 0; m < 64; m++) acc[m] = 0.f;

    #pragma unroll 8
    for (int n = 0; n < 64; n++) {
        float rv = rrow[n];
        const float4* srow = (const float4*)&ssm[n * 64];
        #pragma unroll
        for (int m4 = 0; m4 < 16; m4++) {
            float4 s4 = srow[m4];
            acc[m4 * 4 + 0] += rv * s4.x;
            acc[m4 * 4 + 1] += rv * s4.y;
            acc[m4 * 4 + 2] += rv * s4.z;
            acc[m4 * 4 + 3] += rv * s4.w;
        }
    }
    float wbq = wpow[q];
    #pragma unroll
    for (int m = 0; m < 64; m++) acc[m] *= wbq;

    int jend = q | 31;
    for (int j = 0; j <= jend; j++) {
        float a = 0.f;
        const float4* krow = (const float4*)&ksm[j * 64];
        #pragma unroll
        for (int n4 = 0; n4 < 16; n4++) {
            float4 k4 = krow[n4];
            a += rrow[n4 * 4 + 0] * k4.x + rrow[n4 * 4 + 1] * k4.y
               + rrow[n4 * 4 + 2] * k4.z + rrow[n4 * 4 + 3] * k4.w;
        }
        float coef = (j < q) ? wpow[q - j - 1] : ((j == q) ? u : 0.0f);
        a *= coef;
        const float4* vrow = (const float4*)&vsm[j * 64];
        #pragma unroll
        for (int m4 = 0; m4 < 16; m4++) {
            float4 v4 = vrow[m4];
            acc[m4 * 4 + 0] += a * v4.x;
            acc[m4 * 4 + 1] += a * v4.y;
            acc[m4 * 4 + 2] += a * v4.z;
            acc[m4 * 4 + 3] += a * v4.w;
        }
    }

    float* yo = y + base + (size_t)q * CC;
    #pragma unroll
    for (int m4 = 0; m4 < 16; m4++) {
        float4 o4 = make_float4(acc[m4 * 4 + 0], acc[m4 * 4 + 1], acc[m4 * 4 + 2], acc[m4 * 4 + 3]);
        *(float4*)(yo + m4 * 4) = o4;
    }
}

// ---------------- GroupNorm * g (tf32-rounded output: feeds Wo GEMM) ----------------
__global__ __launch_bounds__(256) void gn_mul_kernel(const float* __restrict__ y,
                                                     const float* __restrict__ gnw,
                                                     const float* __restrict__ gnb,
                                                     const float* __restrict__ g,
                                                     float* __restrict__ yg)
{
    int row = blockIdx.x;
    int tid = threadIdx.x;
    size_t off = (size_t)row * CC;
    float4 v = ((const float4*)(y + off))[tid];
    float s  = v.x + v.y + v.z + v.w;
    float sq = v.x*v.x + v.y*v.y + v.z*v.z + v.w*v.w;
    #pragma unroll
    for (int o = 8; o >= 1; o >>= 1) {
        s  += __shfl_xor_sync(0xffffffffu, s,  o);
        sq += __shfl_xor_sync(0xffffffffu, sq, o);
    }
    float mu   = s * (1.0f / 64.0f);
    float var  = sq * (1.0f / 64.0f) - mu * mu;
    float rstd = rsqrtf(var + EPS_GN);
    float4 ww = ((const float4*)gnw)[tid];
    float4 bb = ((const float4*)gnb)[tid];
    float4 gg = ((const float4*)(g + off))[tid];
    float4 o4;
    o4.x = tf32_rna(((v.x - mu) * rstd * ww.x + bb.x) * gg.x);
    o4.y = tf32_rna(((v.y - mu) * rstd * ww.y + bb.y) * gg.y);
    o4.z = tf32_rna(((v.z - mu) * rstd * ww.z + bb.z) * gg.z);
    o4.w = tf32_rna(((v.w - mu) * rstd * ww.w + bb.w) * gg.w);
    ((float4*)(yg + off))[tid] = o4;
}

// ---------------- host launcher ----------------
extern "C" void kernel_launch(void* const* d_in, const int* in_sizes, int n_in,
                              void* d_out, int out_size)
{
    const float* x      = (const float*)d_in[0];
    const float* ln1w   = (const float*)d_in[1];
    const float* ln1b   = (const float*)d_in[2];
    const float* maak   = (const float*)d_in[3];
    const float* maav   = (const float*)d_in[4];
    const float* maar   = (const float*)d_in[5];
    const float* maag   = (const float*)d_in[6];
    const float* decay  = (const float*)d_in[7];
    const float* faaaa  = (const float*)d_in[8];
    const float* Wr     = (const float*)d_in[9];
    const float* Wk     = (const float*)d_in[10];
    const float* Wv     = (const float*)d_in[11];
    const float* Wg     = (const float*)d_in[12];
    const float* Wo     = (const float*)d_in[13];
    const float* gnw    = (const float*)d_in[14];
    const float* gnb    = (const float*)d_in[15];
    const float* ln2w   = (const float*)d_in[16];
    const float* ln2b   = (const float*)d_in[17];
    const float* cmaak  = (const float*)d_in[18];
    const float* cmaar  = (const float*)d_in[19];
    const float* Wck    = (const float*)d_in[20];
    const float* Wcv    = (const float*)d_in[21];
    const float* Wcr    = (const float*)d_in[22];
    float* out = (float*)d_out;

    float* sc = nullptr;
    cudaGetSymbolAddress((void**)&sc, g_scratch);

    float* xk   = sc + OFF_XK;
    float* xv   = sc + OFF_XV;
    float* xr   = sc + OFF_XR;
    float* xg   = sc + OFF_XG;
    float* rb   = sc + OFF_R;
    float* kb   = sc + OFF_K;
    float* vb   = sc + OFF_V;
    float* gb   = sc + OFF_G;
    float* yb   = sc + OFF_Y;
    float* ygb  = sc + OFF_YG;
    float* x1   = sc + OFF_X1;
    float* xk2  = sc + OFF_XK2;
    float* xr2  = sc + OFF_XR2;
    float* hv   = sc + OFF_HV;
    float* hb   = sc + OFF_H;
    float* Sb   = sc + OFF_S;
    float* STb  = sc + OFF_ST;
    float* WrR  = sc + OFF_WR_R;
    float* WkR  = sc + OFF_WK_R;
    float* WvR  = sc + OFF_WV_R;
    float* WgR  = sc + OFF_WG_R;
    float* WoR  = sc + OFF_WO_R;
    float* WcrR = sc + OFF_WCR_R;
    float* WckR = sc + OFF_WCK_R;
    float* WcvR = sc + OFF_WCV_R;

    cudaFuncSetAttribute(wkv_y_kernel, cudaFuncAttributeMaxDynamicSharedMemorySize, WKV_Y_SMEM);
    cudaFuncSetAttribute(gemm_tc_kernel, cudaFuncAttributeMaxDynamicSharedMemorySize, GEMM_SMEM);

    dim3 g1024(1024 / 128, MTOT / 128);   // (8, 128)
    dim3 g3072(3072 / 128, MTOT / 128);   // (24, 128)
    int n4_1M = (CC * CC) / 4;
    int n4_3M = (3 * CC * CC) / 4;

    // ---- time mix ----
    // launch order keeps ncu capture (-s 5 -c 1) on the first 1024-GEMM
    ln_mix_kernel<4><<<MTOT, 256>>>(x, ln1w, ln1b, maak, maav, maar, maag, xk, xv, xr, xg);
    round_w_kernel<<<n4_1M / 256, 256>>>(Wr, WrR, n4_1M);
    round_w_kernel<<<n4_1M / 256, 256>>>(Wk, WkR, n4_1M);
    round_w_kernel<<<n4_1M / 256, 256>>>(Wv, WvR, n4_1M);
    round_w_kernel<<<n4_1M / 256, 256>>>(Wg, WgR, n4_1M);
    gemm_tc_kernel<<<g1024, 256, GEMM_SMEM>>>(xr, WrR, rb, 1024, 1024, 0, nullptr, nullptr);  // launch #6
    gemm_tc_kernel<<<g1024, 256, GEMM_SMEM>>>(xk, WkR, kb, 1024, 1024, 0, nullptr, nullptr);
    gemm_tc_kernel<<<g1024, 256, GEMM_SMEM>>>(xv, WvR, vb, 1024, 1024, 0, nullptr, nullptr);
    gemm_tc_kernel<<<g1024, 256, GEMM_SMEM>>>(xg, WgR, gb, 1024, 1024, 1, nullptr, nullptr);  // silu

    wkv_s_kernel<<<BB * HH * NCK, 256>>>(kb, vb, decay, Sb);
    wkv_scan_kernel<<<BB * HH, 256>>>(Sb, decay, STb);
    wkv_y_kernel<<<BB * HH * NCK, 256, WKV_Y_SMEM>>>(rb, kb, vb, STb, decay, faaaa, yb);

    gn_mul_kernel<<<MTOT, 256>>>(yb, gnw, gnb, gb, ygb);
    round_w_kernel<<<n4_1M / 256, 256>>>(Wo, WoR, n4_1M);
    gemm_tc_kernel<<<g1024, 256, GEMM_SMEM>>>(ygb, WoR, x1, 1024, 1024, 4, x, nullptr);       // + residual

    // ---- channel mix ----
    ln_mix_kernel<2><<<MTOT, 256>>>(x1, ln2w, ln2b, cmaak, cmaar, nullptr, nullptr,
                                    xk2, xr2, nullptr, nullptr);
    round_w_kernel<<<n4_3M / 256, 256>>>(Wck, WckR, n4_3M);
    round_w_kernel<<<n4_3M / 256, 256>>>(Wcv, WcvR, n4_3M);
    round_w_kernel<<<n4_1M / 256, 256>>>(Wcr, WcrR, n4_1M);
    gemm_tc_kernel<<<g3072, 256, GEMM_SMEM>>>(xk2, WckR, hb, 3072, 1024, 2, nullptr, nullptr); // relu^2
    gemm_tc_kernel<<<g1024, 256, GEMM_SMEM>>>(hb, WcvR, hv, 1024, 3072, 0, nullptr, nullptr);
    gemm_tc_kernel<<<g1024, 256, GEMM_SMEM>>>(xr2, WcrR, out, 1024, 1024, 3, hv, x1);          // sigmoid*hv + x1
}

// round 7
// speedup vs baseline: 5.5774x; 1.4685x over previous
#include <cuda_runtime.h>
#include <cuda_fp16.h>
#include <math.h>
#include <stdint.h>

// ---------------- problem constants ----------------
#define BB 4
#define TT 4096
#define CC 1024
#define HH 16
#define NHD 64
#define QQ 256
#define NCK 16
#define MTOT (BB*TT)          // 16384
#define BTC (BB*TT*CC)        // 16777216
#define EPS_LN 1e-5f
#define EPS_GN (1e-5f*64.0f)

// ---------------- scratch ----------------
#define SCR_TOTAL (19ull*BTC + 8388608ull + 12582912ull)
__device__ float g_scratch[SCR_TOTAL];

#define OFF_XK   (1ull*BTC)      // fp16 buffers (use half the float space)
#define OFF_XV   (2ull*BTC)
#define OFF_XR   (3ull*BTC)
#define OFF_XG   (4ull*BTC)
#define OFF_R    (5ull*BTC)      // fp32
#define OFF_K    (6ull*BTC)
#define OFF_V    (7ull*BTC)
#define OFF_G    (8ull*BTC)
#define OFF_Y    (9ull*BTC)
#define OFF_YG   (10ull*BTC)     // fp16
#define OFF_X1   (11ull*BTC)     // fp32
#define OFF_XK2  (13ull*BTC)     // fp16
#define OFF_XR2  (14ull*BTC)     // fp16
#define OFF_HV   (15ull*BTC)     // fp32
#define OFF_H    (16ull*BTC)     // fp16 [16384,3072]
#define OFF_S    (19ull*BTC)
#define OFF_ST   (19ull*BTC + 4194304ull)
#define OFF_WT   (19ull*BTC + 8388608ull)
#define OFF_WR_R  (OFF_WT + 0ull)
#define OFF_WK_R  (OFF_WT + 1048576ull)
#define OFF_WV_R  (OFF_WT + 2097152ull)
#define OFF_WG_R  (OFF_WT + 3145728ull)
#define OFF_WO_R  (OFF_WT + 4194304ull)
#define OFF_WCR_R (OFF_WT + 5242880ull)
#define OFF_WCK_R (OFF_WT + 6291456ull)
#define OFF_WCV_R (OFF_WT + 9437184ull)

// ---------------- helpers ----------------
__device__ __forceinline__ uint32_t smem_u32(const void* p) {
    uint32_t a;
    asm("{ .reg .u64 t; cvta.to.shared.u64 t, %1; cvt.u32.u64 %0, t; }" : "=r"(a) : "l"(p));
    return a;
}

__device__ __forceinline__ uint32_t pack_f16(float a, float b) {
    __half2 h = __floats2half2_rn(a, b);
    return *(uint32_t*)&h;
}

__device__ __forceinline__ void cp16(uint32_t dst, const void* src) {
    asm volatile("cp.async.cg.shared.global [%0], [%1], 16;" :: "r"(dst), "l"(src) : "memory");
}
#define CP_COMMIT() asm volatile("cp.async.commit_group;" ::: "memory")
#define CP_WAIT_1() asm volatile("cp.async.wait_group 1;" ::: "memory")

// ---------------- weight fp32 -> fp16 ----------------
__global__ __launch_bounds__(256) void cvt_w_kernel(const float* __restrict__ src,
                                                    __half* __restrict__ dst, int n4)
{
    int i = blockIdx.x * 256 + threadIdx.x;
    if (i < n4) {
        float4 v = ((const float4*)src)[i];
        uint2 o;
        o.x = pack_f16(v.x, v.y);
        o.y = pack_f16(v.z, v.w);
        ((uint2*)dst)[i] = o;
    }
}

// ---------------- fused LayerNorm + time-shift mix (fp16 outputs) ----------------
template<int NOUT>
__global__ __launch_bounds__(256) void ln_mix_kernel(const float* __restrict__ x,
                                                     const float* __restrict__ w,
                                                     const float* __restrict__ b,
                                                     const float* __restrict__ m0,
                                                     const float* __restrict__ m1,
                                                     const float* __restrict__ m2,
                                                     const float* __restrict__ m3,
                                                     __half* __restrict__ o0,
                                                     __half* __restrict__ o1,
                                                     __half* __restrict__ o2,
                                                     __half* __restrict__ o3)
{
    int row = blockIdx.x;
    int t = row % TT;
    int tid = threadIdx.x;
    size_t off = (size_t)row * CC;
    float4 cur = ((const float4*)(x + off))[tid];
    float4 prv = make_float4(0.f, 0.f, 0.f, 0.f);
    if (t > 0) prv = ((const float4*)(x + off - CC))[tid];

    float s0 = cur.x + cur.y + cur.z + cur.w;
    float q0 = cur.x*cur.x + cur.y*cur.y + cur.z*cur.z + cur.w*cur.w;
    float s1 = prv.x + prv.y + prv.z + prv.w;
    float q1 = prv.x*prv.x + prv.y*prv.y + prv.z*prv.z + prv.w*prv.w;
    #pragma unroll
    for (int o = 16; o >= 1; o >>= 1) {
        s0 += __shfl_xor_sync(0xffffffffu, s0, o);
        q0 += __shfl_xor_sync(0xffffffffu, q0, o);
        s1 += __shfl_xor_sync(0xffffffffu, s1, o);
        q1 += __shfl_xor_sync(0xffffffffu, q1, o);
    }
    __shared__ float red[4][8];
    int wid = tid >> 5, lane = tid & 31;
    if (lane == 0) { red[0][wid] = s0; red[1][wid] = q0; red[2][wid] = s1; red[3][wid] = q1; }
    __syncthreads();
    if (tid == 0) {
        float a0 = 0, a1 = 0, a2 = 0, a3 = 0;
        #pragma unroll
        for (int i = 0; i < 8; i++) { a0 += red[0][i]; a1 += red[1][i]; a2 += red[2][i]; a3 += red[3][i]; }
        red[0][0] = a0; red[1][0] = a1; red[2][0] = a2; red[3][0] = a3;
    }
    __syncthreads();
    float mu0 = red[0][0] * (1.0f / CC);
    float rs0 = rsqrtf(red[1][0] * (1.0f / CC) - mu0 * mu0 + EPS_LN);
    float mu1 = red[2][0] * (1.0f / CC);
    float rs1 = rsqrtf(red[3][0] * (1.0f / CC) - mu1 * mu1 + EPS_LN);

    float4 ww = ((const float4*)w)[tid];
    float4 bb = ((const float4*)b)[tid];
    float4 lc, lp;
    lc.x = (cur.x - mu0) * rs0 * ww.x + bb.x;
    lc.y = (cur.y - mu0) * rs0 * ww.y + bb.y;
    lc.z = (cur.z - mu0) * rs0 * ww.z + bb.z;
    lc.w = (cur.w - mu0) * rs0 * ww.w + bb.w;
    if (t > 0) {
        lp.x = (prv.x - mu1) * rs1 * ww.x + bb.x;
        lp.y = (prv.y - mu1) * rs1 * ww.y + bb.y;
        lp.z = (prv.z - mu1) * rs1 * ww.z + bb.z;
        lp.w = (prv.w - mu1) * rs1 * ww.w + bb.w;
    } else {
        lp = make_float4(0.f, 0.f, 0.f, 0.f);
    }
    float4 xx = make_float4(lp.x - lc.x, lp.y - lc.y, lp.z - lc.z, lp.w - lc.w);

    float4 a;
    uint2 o;
    a = ((const float4*)m0)[tid];
    o.x = pack_f16(lc.x + xx.x * a.x, lc.y + xx.y * a.y);
    o.y = pack_f16(lc.z + xx.z * a.z, lc.w + xx.w * a.w);
    ((uint2*)(o0 + off))[tid] = o;
    a = ((const float4*)m1)[tid];
    o.x = pack_f16(lc.x + xx.x * a.x, lc.y + xx.y * a.y);
    o.y = pack_f16(lc.z + xx.z * a.z, lc.w + xx.w * a.w);
    ((uint2*)(o1 + off))[tid] = o;
    if (NOUT == 4) {
        a = ((const float4*)m2)[tid];
        o.x = pack_f16(lc.x + xx.x * a.x, lc.y + xx.y * a.y);
        o.y = pack_f16(lc.z + xx.z * a.z, lc.w + xx.w * a.w);
        ((uint2*)(o2 + off))[tid] = o;
        a = ((const float4*)m3)[tid];
        o.x = pack_f16(lc.x + xx.x * a.x, lc.y + xx.y * a.y);
        o.y = pack_f16(lc.z + xx.z * a.z, lc.w + xx.w * a.w);
        ((uint2*)(o3 + off))[tid] = o;
    }
}

// ---------------- fp16 tensor-core GEMM (cp.async 2-stage, k-tile 64) ----------------
// Cout[M,Nn] = A[M,K] @ W[Nn,K]^T + epilogue.  A,W fp16; acc fp32.
// 128x128 tiles, 256 threads (8 warps = 2x4), warp tile 64x32 = 4x4 m16n8k16.
// Stage: A rows 0..127 then W rows 0..127, 64 fp16/row, row stride 36 words.
// epi: 0 plain, 1 silu, 2 relu^2 -> fp16 out, 3 sigmoid()*aux1+aux2, 4 +aux1
#define STG_WORDS 9216                        // 256 rows * 36 uint32
#define GEMM_SMEM (2 * STG_WORDS * 4)         // 73728 bytes

__device__ __forceinline__ void mma_f16(float c[4],
                                        const uint32_t a[4],
                                        const uint32_t b[2])
{
    asm volatile(
        "mma.sync.aligned.m16n8k16.row.col.f32.f16.f16.f32 "
        "{%0,%1,%2,%3}, {%4,%5,%6,%7}, {%8,%9}, {%0,%1,%2,%3};\n"
        : "+f"(c[0]), "+f"(c[1]), "+f"(c[2]), "+f"(c[3])
        : "r"(a[0]), "r"(a[1]), "r"(a[2]), "r"(a[3]),
          "r"(b[0]), "r"(b[1]));
}

__device__ __forceinline__ float gemm_epi(float vv, int epi, const float* aux1,
                                          const float* aux2, size_t o)
{
    if (epi == 1) {
        vv = vv / (1.f + expf(-vv));
    } else if (epi == 3) {
        vv = 1.f / (1.f + expf(-vv));
        vv = vv * aux1[o] + aux2[o];
    } else if (epi == 4) {
        vv = vv + aux1[o];
    }
    return vv;
}

__global__ void __launch_bounds__(256, 2)
gemm_hf_kernel(const __half* __restrict__ A, const __half* __restrict__ W,
               float* __restrict__ Co, __half* __restrict__ Coh,
               int Nn, int K, int epi,
               const float* __restrict__ aux1, const float* __restrict__ aux2)
{
    extern __shared__ uint32_t smw[];
    int tid = threadIdx.x;
    int n0 = blockIdx.x * 128;
    int m0 = blockIdx.y * 128;
    int wid = tid >> 5, lane = tid & 31;
    int wm = wid >> 2, wn = wid & 3;
    int gid = lane >> 2, tg = lane & 3;

    // async-copy mapping: row 64 fp16 = 8 chunks of 16B
    int j  = tid & 7;
    int r0 = tid >> 3;           // 0..31, +32*i
    const __half* pA = A + ((size_t)m0 + r0) * K + j * 8;
    const __half* pW = W + ((size_t)n0 + r0) * K + j * 8;
    uint32_t smb = smem_u32(smw);
    uint32_t dstA = smb + (uint32_t)(r0 * 36 + j * 4) * 4u;
    uint32_t dstW = dstA + 4608u * 4u;

    float acc[4][4][4];
    #pragma unroll
    for (int mi = 0; mi < 4; mi++)
        #pragma unroll
        for (int ni = 0; ni < 4; ni++)
            #pragma unroll
            for (int e = 0; e < 4; e++) acc[mi][ni][e] = 0.f;

    int NC = K >> 6;

    #pragma unroll
    for (int s = 0; s < 2; s++) {
        uint32_t so = (uint32_t)(s * STG_WORDS) * 4u;
        int kf = s * 64;
        #pragma unroll
        for (int i = 0; i < 4; i++) {
            cp16(dstA + so + (uint32_t)(i * 32 * 36) * 4u, pA + (size_t)(i * 32) * K + kf);
            cp16(dstW + so + (uint32_t)(i * 32 * 36) * 4u, pW + (size_t)(i * 32) * K + kf);
        }
        CP_COMMIT();
    }

    int aoff[4], boff[4];
    #pragma unroll
    for (int mi = 0; mi < 4; mi++) aoff[mi] = (wm * 64 + mi * 16 + gid) * 36 + tg;
    #pragma unroll
    for (int ni = 0; ni < 4; ni++) boff[ni] = 4608 + (wn * 32 + ni * 8 + gid) * 36 + tg;

    for (int t = 0; t < NC; t++) {
        CP_WAIT_1();
        __syncthreads();
        const uint32_t* St = smw + (t & 1) * STG_WORDS;

        #pragma unroll
        for (int kk = 0; kk < 4; kk++) {
            int ks = kk * 8;
            uint32_t af[4][4];
            uint32_t bf[4][2];
            #pragma unroll
            for (int mi = 0; mi < 4; mi++) {
                const uint32_t* ap = St + aoff[mi] + ks;
                af[mi][0] = ap[0];
                af[mi][1] = ap[8 * 36];
                af[mi][2] = ap[4];
                af[mi][3] = ap[8 * 36 + 4];
            }
            #pragma unroll
            for (int ni = 0; ni < 4; ni++) {
                const uint32_t* bp = St + boff[ni] + ks;
                bf[ni][0] = bp[0];
                bf[ni][1] = bp[4];
            }
            #pragma unroll
            for (int mi = 0; mi < 4; mi++)
                #pragma unroll
                for (int ni = 0; ni < 4; ni++)
                    mma_f16(acc[mi][ni], af[mi], bf[ni]);
        }
        __syncthreads();

        int lc = t + 2;
        if (lc < NC) {
            uint32_t so = (uint32_t)((t & 1) * STG_WORDS) * 4u;
            int kf = lc * 64;
            #pragma unroll
            for (int i = 0; i < 4; i++) {
                cp16(dstA + so + (uint32_t)(i * 32 * 36) * 4u, pA + (size_t)(i * 32) * K + kf);
                cp16(dstW + so + (uint32_t)(i * 32 * 36) * 4u, pW + (size_t)(i * 32) * K + kf);
            }
        }
        CP_COMMIT();
    }

    // epilogue
    #pragma unroll
    for (int mi = 0; mi < 4; mi++) {
        int row0 = m0 + wm * 64 + mi * 16 + gid;
        #pragma unroll
        for (int ni = 0; ni < 4; ni++) {
            int col0 = n0 + wn * 32 + ni * 8 + tg * 2;
            size_t o0 = (size_t)row0 * Nn + col0;
            size_t o1 = (size_t)(row0 + 8) * Nn + col0;
            if (epi == 2) {
                // relu^2 -> fp16 output
                float a0 = fmaxf(acc[mi][ni][0], 0.f); a0 *= a0;
                float a1 = fmaxf(acc[mi][ni][1], 0.f); a1 *= a1;
                float a2 = fmaxf(acc[mi][ni][2], 0.f); a2 *= a2;
                float a3 = fmaxf(acc[mi][ni][3], 0.f); a3 *= a3;
                *(uint32_t*)(Coh + o0) = pack_f16(a0, a1);
                *(uint32_t*)(Coh + o1) = pack_f16(a2, a3);
            } else {
                float2 v0, v1;
                v0.x = gemm_epi(acc[mi][ni][0], epi, aux1, aux2, o0);
                v0.y = gemm_epi(acc[mi][ni][1], epi, aux1, aux2, o0 + 1);
                v1.x = gemm_epi(acc[mi][ni][2], epi, aux1, aux2, o1);
                v1.y = gemm_epi(acc[mi][ni][3], epi, aux1, aux2, o1 + 1);
                *(float2*)(Co + o0) = v0;
                *(float2*)(Co + o1) = v1;
            }
        }
    }
}

// ---------------- WKV: per-chunk state contribution S = (k*wk) @ v ----------------
__global__ __launch_bounds__(256) void wkv_s_kernel(const float* __restrict__ k,
                                                    const float* __restrict__ v,
                                                    const float* __restrict__ decay,
                                                    float* __restrict__ S)
{
    int blk = blockIdx.x;
    int c = blk % NCK;
    int h = (blk / NCK) % HH;
    int b = blk / (NCK * HH);
    __shared__ float ksm[64][64];
    __shared__ float vsm[64][64];
    __shared__ float wpow[256];
    int tid = threadIdx.x;
    float ew = expf(decay[h]);
    wpow[tid] = expf(-ew * (float)tid);
    int n  = tid >> 2;
    int mg = (tid & 3) * 16;
    float acc[16];
    #pragma unroll
    for (int jj = 0; jj < 16; jj++) acc[jj] = 0.f;

    size_t base = ((size_t)b * TT + (size_t)c * QQ) * CC + (size_t)h * NHD;

    for (int qc = 0; qc < 4; qc++) {
        __syncthreads();
        for (int l = tid; l < 64 * 16; l += 256) {
            int qq = l >> 4;
            int f  = (l & 15) * 4;
            *(float4*)&ksm[qq][f] = *(const float4*)(k + base + (size_t)(qc * 64 + qq) * CC + f);
            *(float4*)&vsm[qq][f] = *(const float4*)(v + base + (size_t)(qc * 64 + qq) * CC + f);
        }
        __syncthreads();
        #pragma unroll 4
        for (int qq = 0; qq < 64; qq++) {
            float kw = ksm[qq][n] * wpow[255 - (qc * 64 + qq)];
            const float4* vr = (const float4*)&vsm[qq][mg];
            float4 v0 = vr[0], v1 = vr[1], v2 = vr[2], v3 = vr[3];
            acc[0]  += kw * v0.x; acc[1]  += kw * v0.y; acc[2]  += kw * v0.z; acc[3]  += kw * v0.w;
            acc[4]  += kw * v1.x; acc[5]  += kw * v1.y; acc[6]  += kw * v1.z; acc[7]  += kw * v1.w;
            acc[8]  += kw * v2.x; acc[9]  += kw * v2.y; acc[10] += kw * v2.z; acc[11] += kw * v2.w;
            acc[12] += kw * v3.x; acc[13] += kw * v3.y; acc[14] += kw * v3.z; acc[15] += kw * v3.w;
        }
    }
    float* Sp = S + (size_t)blk * 4096 + n * 64 + mg;
    #pragma unroll
    for (int jj = 0; jj < 16; jj++) Sp[jj] = acc[jj];
}

// ---------------- WKV: inter-chunk prefix scan ----------------
__global__ __launch_bounds__(256) void wkv_scan_kernel(const float* __restrict__ S,
                                                       const float* __restrict__ decay,
                                                       float* __restrict__ ST)
{
    int bh = blockIdx.x;
    int h = bh % HH;
    float ws = expf(-expf(decay[h]) * 256.0f);
    int tid = threadIdx.x;
    size_t b0 = (size_t)bh * NCK * 4096;
    for (int r = 0; r < 16; r++) {
        int e = tid + r * 256;
        float st = 0.f;
        #pragma unroll
        for (int c = 0; c < NCK; c++) {
            ST[b0 + (size_t)c * 4096 + e] = st;
            st = ws * st + S[b0 + (size_t)c * 4096 + e];
        }
    }
}

// ---------------- WKV: per-chunk output ----------------
#define WKV_Y_SMEM ((256*64*2 + 4096 + 256) * 4)
__global__ __launch_bounds__(256) void wkv_y_kernel(const float* __restrict__ r,
                                                    const float* __restrict__ k,
                                                    const float* __restrict__ v,
                                                    const float* __restrict__ ST,
                                                    const float* __restrict__ decay,
                                                    const float* __restrict__ faaaa,
                                                    float* __restrict__ y)
{
    extern __shared__ float sm[];
    float* ksm  = sm;
    float* vsm  = sm + 16384;
    float* ssm  = sm + 32768;
    float* wpow = sm + 36864;

    int blk = blockIdx.x;
    int c = blk % NCK;
    int h = (blk / NCK) % HH;
    int b = blk / (NCK * HH);
    int tid = threadIdx.x;

    float ew = expf(decay[h]);
    float u  = faaaa[h];
    wpow[tid] = expf(-ew * (float)tid);

    size_t base = ((size_t)b * TT + (size_t)c * QQ) * CC + (size_t)h * NHD;

    for (int l = tid; l < 256 * 16; l += 256) {
        int qq = l >> 4;
        int f  = (l & 15) * 4;
        *(float4*)&ksm[qq * 64 + f] = *(const float4*)(k + base + (size_t)qq * CC + f);
        *(float4*)&vsm[qq * 64 + f] = *(const float4*)(v + base + (size_t)qq * CC + f);
    }
    size_t sbase = (size_t)blk * 4096;
    for (int l = tid; l < 1024; l += 256)
        *(float4*)&ssm[l * 4] = *(const float4*)(ST + sbase + (size_t)l * 4);
    __syncthreads();

    int q = tid;
    float rrow[64];
    {
        const float4* rg = (const float4*)(r + base + (size_t)q * CC);
        #pragma unroll
        for (int f = 0; f < 16; f++) {
            float4 t4 = rg[f];
            rrow[f * 4 + 0] = t4.x; rrow[f * 4 + 1] = t4.y;
            rrow[f * 4 + 2] = t4.z; rrow[f * 4 + 3] = t4.w;
        }
    }
    float acc[64];
    #pragma unroll
    for (int m = 0; m < 64; m++) acc[m] = 0.f;

    #pragma unroll 8
    for (int n = 0; n < 64; n++) {
        float rv = rrow[n];
        const float4* srow = (const float4*)&ssm[n * 64];
        #pragma unroll
        for (int m4 = 0; m4 < 16; m4++) {
            float4 s4 = srow[m4];
            acc[m4 * 4 + 0] += rv * s4.x;
            acc[m4 * 4 + 1] += rv * s4.y;
            acc[m4 * 4 + 2] += rv * s4.z;
            acc[m4 * 4 + 3] += rv * s4.w;
        }
    }
    float wbq = wpow[q];
    #pragma unroll
    for (int m = 0; m < 64; m++) acc[m] *= wbq;

    int jend = q | 31;
    for (int j = 0; j <= jend; j++) {
        float a = 0.f;
        const float4* krow = (const float4*)&ksm[j * 64];
        #pragma unroll
        for (int n4 = 0; n4 < 16; n4++) {
            float4 k4 = krow[n4];
            a += rrow[n4 * 4 + 0] * k4.x + rrow[n4 * 4 + 1] * k4.y
               + rrow[n4 * 4 + 2] * k4.z + rrow[n4 * 4 + 3] * k4.w;
        }
        float coef = (j < q) ? wpow[q - j - 1] : ((j == q) ? u : 0.0f);
        a *= coef;
        const float4* vrow = (const float4*)&vsm[j * 64];
        #pragma unroll
        for (int m4 = 0; m4 < 16; m4++) {
            float4 v4 = vrow[m4];
            acc[m4 * 4 + 0] += a * v4.x;
            acc[m4 * 4 + 1] += a * v4.y;
            acc[m4 * 4 + 2] += a * v4.z;
            acc[m4 * 4 + 3] += a * v4.w;
        }
    }

    float* yo = y + base + (size_t)q * CC;
    #pragma unroll
    for (int m4 = 0; m4 < 16; m4++) {
        float4 o4 = make_float4(acc[m4 * 4 + 0], acc[m4 * 4 + 1], acc[m4 * 4 + 2], acc[m4 * 4 + 3]);
        *(float4*)(yo + m4 * 4) = o4;
    }
}

// ---------------- GroupNorm * g (fp16 output: feeds Wo GEMM) ----------------
__global__ __launch_bounds__(256) void gn_mul_kernel(const float* __restrict__ y,
                                                     const float* __restrict__ gnw,
                                                     const float* __restrict__ gnb,
                                                     const float* __restrict__ g,
                                                     __half* __restrict__ yg)
{
    int row = blockIdx.x;
    int tid = threadIdx.x;
    size_t off = (size_t)row * CC;
    float4 v = ((const float4*)(y + off))[tid];
    float s  = v.x + v.y + v.z + v.w;
    float sq = v.x*v.x + v.y*v.y + v.z*v.z + v.w*v.w;
    #pragma unroll
    for (int o = 8; o >= 1; o >>= 1) {
        s  += __shfl_xor_sync(0xffffffffu, s,  o);
        sq += __shfl_xor_sync(0xffffffffu, sq, o);
    }
    float mu   = s * (1.0f / 64.0f);
    float var  = sq * (1.0f / 64.0f) - mu * mu;
    float rstd = rsqrtf(var + EPS_GN);
    float4 ww = ((const float4*)gnw)[tid];
    float4 bb = ((const float4*)gnb)[tid];
    float4 gg = ((const float4*)(g + off))[tid];
    uint2 o4;
    o4.x = pack_f16(((v.x - mu) * rstd * ww.x + bb.x) * gg.x,
                    ((v.y - mu) * rstd * ww.y + bb.y) * gg.y);
    o4.y = pack_f16(((v.z - mu) * rstd * ww.z + bb.z) * gg.z,
                    ((v.w - mu) * rstd * ww.w + bb.w) * gg.w);
    ((uint2*)(yg + off))[tid] = o4;
}

// ---------------- host launcher ----------------
extern "C" void kernel_launch(void* const* d_in, const int* in_sizes, int n_in,
                              void* d_out, int out_size)
{
    const float* x      = (const float*)d_in[0];
    const float* ln1w   = (const float*)d_in[1];
    const float* ln1b   = (const float*)d_in[2];
    const float* maak   = (const float*)d_in[3];
    const float* maav   = (const float*)d_in[4];
    const float* maar   = (const float*)d_in[5];
    const float* maag   = (const float*)d_in[6];
    const float* decay  = (const float*)d_in[7];
    const float* faaaa  = (const float*)d_in[8];
    const float* Wr     = (const float*)d_in[9];
    const float* Wk     = (const float*)d_in[10];
    const float* Wv     = (const float*)d_in[11];
    const float* Wg     = (const float*)d_in[12];
    const float* Wo     = (const float*)d_in[13];
    const float* gnw    = (const float*)d_in[14];
    const float* gnb    = (const float*)d_in[15];
    const float* ln2w   = (const float*)d_in[16];
    const float* ln2b   = (const float*)d_in[17];
    const float* cmaak  = (const float*)d_in[18];
    const float* cmaar  = (const float*)d_in[19];
    const float* Wck    = (const float*)d_in[20];
    const float* Wcv    = (const float*)d_in[21];
    const float* Wcr    = (const float*)d_in[22];
    float* out = (float*)d_out;

    float* sc = nullptr;
    cudaGetSymbolAddress((void**)&sc, g_scratch);

    __half* xk   = (__half*)(sc + OFF_XK);
    __half* xv   = (__half*)(sc + OFF_XV);
    __half* xr   = (__half*)(sc + OFF_XR);
    __half* xg   = (__half*)(sc + OFF_XG);
    float* rb   = sc + OFF_R;
    float* kb   = sc + OFF_K;
    float* vb   = sc + OFF_V;
    float* gb   = sc + OFF_G;
    float* yb   = sc + OFF_Y;
    __half* ygb = (__half*)(sc + OFF_YG);
    float* x1   = sc + OFF_X1;
    __half* xk2 = (__half*)(sc + OFF_XK2);
    __half* xr2 = (__half*)(sc + OFF_XR2);
    float* hv   = sc + OFF_HV;
    __half* hb  = (__half*)(sc + OFF_H);
    float* Sb   = sc + OFF_S;
    float* STb  = sc + OFF_ST;
    __half* WrR  = (__half*)(sc + OFF_WR_R);
    __half* WkR  = (__half*)(sc + OFF_WK_R);
    __half* WvR  = (__half*)(sc + OFF_WV_R);
    __half* WgR  = (__half*)(sc + OFF_WG_R);
    __half* WoR  = (__half*)(sc + OFF_WO_R);
    __half* WcrR = (__half*)(sc + OFF_WCR_R);
    __half* WckR = (__half*)(sc + OFF_WCK_R);
    __half* WcvR = (__half*)(sc + OFF_WCV_R);

    cudaFuncSetAttribute(wkv_y_kernel, cudaFuncAttributeMaxDynamicSharedMemorySize, WKV_Y_SMEM);
    cudaFuncSetAttribute(gemm_hf_kernel, cudaFuncAttributeMaxDynamicSharedMemorySize, GEMM_SMEM);

    dim3 g1024(1024 / 128, MTOT / 128);   // (8, 128)
    dim3 g3072(3072 / 128, MTOT / 128);   // (24, 128)
    int n4_1M = (CC * CC) / 4;
    int n4_3M = (3 * CC * CC) / 4;

    // ---- time mix ----
    ln_mix_kernel<4><<<MTOT, 256>>>(x, ln1w, ln1b, maak, maav, maar, maag, xk, xv, xr, xg);
    cvt_w_kernel<<<n4_1M / 256, 256>>>(Wr, WrR, n4_1M);
    cvt_w_kernel<<<n4_1M / 256, 256>>>(Wk, WkR, n4_1M);
    cvt_w_kernel<<<n4_1M / 256, 256>>>(Wv, WvR, n4_1M);
    cvt_w_kernel<<<n4_1M / 256, 256>>>(Wg, WgR, n4_1M);
    gemm_hf_kernel<<<g1024, 256, GEMM_SMEM>>>(xr, WrR, rb, nullptr, 1024, 1024, 0, nullptr, nullptr);
    gemm_hf_kernel<<<g1024, 256, GEMM_SMEM>>>(xk, WkR, kb, nullptr, 1024, 1024, 0, nullptr, nullptr);
    gemm_hf_kernel<<<g1024, 256, GEMM_SMEM>>>(xv, WvR, vb, nullptr, 1024, 1024, 0, nullptr, nullptr);
    gemm_hf_kernel<<<g1024, 256, GEMM_SMEM>>>(xg, WgR, gb, nullptr, 1024, 1024, 1, nullptr, nullptr); // silu

    wkv_s_kernel<<<BB * HH * NCK, 256>>>(kb, vb, decay, Sb);
    wkv_scan_kernel<<<BB * HH, 256>>>(Sb, decay, STb);
    wkv_y_kernel<<<BB * HH * NCK, 256, WKV_Y_SMEM>>>(rb, kb, vb, STb, decay, faaaa, yb);

    gn_mul_kernel<<<MTOT, 256>>>(yb, gnw, gnb, gb, ygb);
    cvt_w_kernel<<<n4_1M / 256, 256>>>(Wo, WoR, n4_1M);
    gemm_hf_kernel<<<g1024, 256, GEMM_SMEM>>>(ygb, WoR, x1, nullptr, 1024, 1024, 4, x, nullptr); // + residual

    // ---- channel mix ----
    ln_mix_kernel<2><<<MTOT, 256>>>(x1, ln2w, ln2b, cmaak, cmaar, nullptr, nullptr,
                                    xk2, xr2, nullptr, nullptr);
    cvt_w_kernel<<<n4_3M / 256, 256>>>(Wck, WckR, n4_3M);
    cvt_w_kernel<<<n4_3M / 256, 256>>>(Wcv, WcvR, n4_3M);
    cvt_w_kernel<<<n4_1M / 256, 256>>>(Wcr, WcrR, n4_1M);
    gemm_hf_kernel<<<g3072, 256, GEMM_SMEM>>>(xk2, WckR, nullptr, hb, 3072, 1024, 2, nullptr, nullptr); // relu^2 -> fp16
    gemm_hf_kernel<<<g1024, 256, GEMM_SMEM>>>(hb, WcvR, hv, nullptr, 1024, 3072, 0, nullptr, nullptr);
    gemm_hf_kernel<<<g1024, 256, GEMM_SMEM>>>(xr2, WcrR, out, nullptr, 1024, 1024, 3, hv, x1); // sigmoid*hv + x1
}

// round 8
// speedup vs baseline: 5.6968x; 1.0214x over previous
#include <cuda_runtime.h>
#include <cuda_fp16.h>
#include <math.h>
#include <stdint.h>

// ---------------- problem constants ----------------
#define BB 4
#define TT 4096
#define CC 1024
#define HH 16
#define NHD 64
#define QQ 256
#define NCK 16
#define MTOT (BB*TT)          // 16384
#define BTC (BB*TT*CC)        // 16777216
#define EPS_LN 1e-5f
#define EPS_GN (1e-5f*64.0f)

// ---------------- scratch ----------------
#define SCR_TOTAL (19ull*BTC + 8388608ull + 12582912ull)
__device__ float g_scratch[SCR_TOTAL];

#define OFF_XK   (1ull*BTC)      // fp16 buffers
#define OFF_XV   (2ull*BTC)
#define OFF_XR   (3ull*BTC)
#define OFF_XG   (4ull*BTC)
#define OFF_R    (5ull*BTC)      // fp32
#define OFF_K    (6ull*BTC)
#define OFF_V    (7ull*BTC)
#define OFF_G    (8ull*BTC)
#define OFF_Y    (9ull*BTC)
#define OFF_YG   (10ull*BTC)     // fp16
#define OFF_X1   (11ull*BTC)     // fp32
#define OFF_XK2  (13ull*BTC)     // fp16
#define OFF_XR2  (14ull*BTC)     // fp16
#define OFF_HV   (15ull*BTC)     // fp32
#define OFF_H    (16ull*BTC)     // fp16 [16384,3072]
#define OFF_S    (19ull*BTC)
#define OFF_ST   (19ull*BTC + 4194304ull)
#define OFF_WT   (19ull*BTC + 8388608ull)
#define OFF_WR_R  (OFF_WT + 0ull)
#define OFF_WK_R  (OFF_WT + 1048576ull)
#define OFF_WV_R  (OFF_WT + 2097152ull)
#define OFF_WG_R  (OFF_WT + 3145728ull)
#define OFF_WO_R  (OFF_WT + 4194304ull)
#define OFF_WCR_R (OFF_WT + 5242880ull)
#define OFF_WCK_R (OFF_WT + 6291456ull)
#define OFF_WCV_R (OFF_WT + 9437184ull)

// ---------------- helpers ----------------
__device__ __forceinline__ uint32_t smem_u32(const void* p) {
    uint32_t a;
    asm("{ .reg .u64 t; cvta.to.shared.u64 t, %1; cvt.u32.u64 %0, t; }" : "=r"(a) : "l"(p));
    return a;
}

__device__ __forceinline__ uint32_t pack_f16(float a, float b) {
    __half2 h = __floats2half2_rn(a, b);
    return *(uint32_t*)&h;
}

__device__ __forceinline__ void cp16(uint32_t dst, const void* src) {
    asm volatile("cp.async.cg.shared.global [%0], [%1], 16;" :: "r"(dst), "l"(src) : "memory");
}
#define CP_COMMIT() asm volatile("cp.async.commit_group;" ::: "memory")
#define CP_WAIT_1() asm volatile("cp.async.wait_group 1;" ::: "memory")

// ---------------- weight fp32 -> fp16 ----------------
__global__ __launch_bounds__(256) void cvt_w_kernel(const float* __restrict__ src,
                                                    __half* __restrict__ dst, int n4)
{
    int i = blockIdx.x * 256 + threadIdx.x;
    if (i < n4) {
        float4 v = ((const float4*)src)[i];
        uint2 o;
        o.x = pack_f16(v.x, v.y);
        o.y = pack_f16(v.z, v.w);
        ((uint2*)dst)[i] = o;
    }
}

// ---------------- fused LayerNorm + time-shift mix (fp16 outputs) ----------------
template<int NOUT>
__global__ __launch_bounds__(256) void ln_mix_kernel(const float* __restrict__ x,
                                                     const float* __restrict__ w,
                                                     const float* __restrict__ b,
                                                     const float* __restrict__ m0,
                                                     const float* __restrict__ m1,
                                                     const float* __restrict__ m2,
                                                     const float* __restrict__ m3,
                                                     __half* __restrict__ o0,
                                                     __half* __restrict__ o1,
                                                     __half* __restrict__ o2,
                                                     __half* __restrict__ o3)
{
    int row = blockIdx.x;
    int t = row % TT;
    int tid = threadIdx.x;
    size_t off = (size_t)row * CC;
    float4 cur = ((const float4*)(x + off))[tid];
    float4 prv = make_float4(0.f, 0.f, 0.f, 0.f);
    if (t > 0) prv = ((const float4*)(x + off - CC))[tid];

    float s0 = cur.x + cur.y + cur.z + cur.w;
    float q0 = cur.x*cur.x + cur.y*cur.y + cur.z*cur.z + cur.w*cur.w;
    float s1 = prv.x + prv.y + prv.z + prv.w;
    float q1 = prv.x*prv.x + prv.y*prv.y + prv.z*prv.z + prv.w*prv.w;
    #pragma unroll
    for (int o = 16; o >= 1; o >>= 1) {
        s0 += __shfl_xor_sync(0xffffffffu, s0, o);
        q0 += __shfl_xor_sync(0xffffffffu, q0, o);
        s1 += __shfl_xor_sync(0xffffffffu, s1, o);
        q1 += __shfl_xor_sync(0xffffffffu, q1, o);
    }
    __shared__ float red[4][8];
    int wid = tid >> 5, lane = tid & 31;
    if (lane == 0) { red[0][wid] = s0; red[1][wid] = q0; red[2][wid] = s1; red[3][wid] = q1; }
    __syncthreads();
    if (tid == 0) {
        float a0 = 0, a1 = 0, a2 = 0, a3 = 0;
        #pragma unroll
        for (int i = 0; i < 8; i++) { a0 += red[0][i]; a1 += red[1][i]; a2 += red[2][i]; a3 += red[3][i]; }
        red[0][0] = a0; red[1][0] = a1; red[2][0] = a2; red[3][0] = a3;
    }
    __syncthreads();
    float mu0 = red[0][0] * (1.0f / CC);
    float rs0 = rsqrtf(red[1][0] * (1.0f / CC) - mu0 * mu0 + EPS_LN);
    float mu1 = red[2][0] * (1.0f / CC);
    float rs1 = rsqrtf(red[3][0] * (1.0f / CC) - mu1 * mu1 + EPS_LN);

    float4 ww = ((const float4*)w)[tid];
    float4 bb = ((const float4*)b)[tid];
    float4 lc, lp;
    lc.x = (cur.x - mu0) * rs0 * ww.x + bb.x;
    lc.y = (cur.y - mu0) * rs0 * ww.y + bb.y;
    lc.z = (cur.z - mu0) * rs0 * ww.z + bb.z;
    lc.w = (cur.w - mu0) * rs0 * ww.w + bb.w;
    if (t > 0) {
        lp.x = (prv.x - mu1) * rs1 * ww.x + bb.x;
        lp.y = (prv.y - mu1) * rs1 * ww.y + bb.y;
        lp.z = (prv.z - mu1) * rs1 * ww.z + bb.z;
        lp.w = (prv.w - mu1) * rs1 * ww.w + bb.w;
    } else {
        lp = make_float4(0.f, 0.f, 0.f, 0.f);
    }
    float4 xx = make_float4(lp.x - lc.x, lp.y - lc.y, lp.z - lc.z, lp.w - lc.w);

    float4 a;
    uint2 o;
    a = ((const float4*)m0)[tid];
    o.x = pack_f16(lc.x + xx.x * a.x, lc.y + xx.y * a.y);
    o.y = pack_f16(lc.z + xx.z * a.z, lc.w + xx.w * a.w);
    ((uint2*)(o0 + off))[tid] = o;
    a = ((const float4*)m1)[tid];
    o.x = pack_f16(lc.x + xx.x * a.x, lc.y + xx.y * a.y);
    o.y = pack_f16(lc.z + xx.z * a.z, lc.w + xx.w * a.w);
    ((uint2*)(o1 + off))[tid] = o;
    if (NOUT == 4) {
        a = ((const float4*)m2)[tid];
        o.x = pack_f16(lc.x + xx.x * a.x, lc.y + xx.y * a.y);
        o.y = pack_f16(lc.z + xx.z * a.z, lc.w + xx.w * a.w);
        ((uint2*)(o2 + off))[tid] = o;
        a = ((const float4*)m3)[tid];
        o.x = pack_f16(lc.x + xx.x * a.x, lc.y + xx.y * a.y);
        o.y = pack_f16(lc.z + xx.z * a.z, lc.w + xx.w * a.w);
        ((uint2*)(o3 + off))[tid] = o;
    }
}

// ---------------- fp16 tensor-core GEMM (cp.async 2-stage, ldmatrix, k-tile 64) ----------------
// Cout[M,Nn] = A[M,K] @ W[Nn,K]^T + epilogue.  A,W fp16; acc fp32.
// 128x128 tiles, 256 threads (8 warps = 2x4), warp tile 64x32 = 4x4 m16n8k16.
// Stage: A rows 0..127 then W rows 0..127, 64 fp16/row, row stride 36 words (144B,
// conflict-free for both cp.async stores and ldmatrix 8-lane phases).
// epi: 0 plain, 1 silu, 2 relu^2 -> fp16 out, 3 sigmoid()*aux1+aux2, 4 +aux1
#define STG_WORDS 9216                        // 256 rows * 36 uint32
#define GEMM_SMEM (2 * STG_WORDS * 4)         // 73728 bytes

__device__ __forceinline__ void mma_f16(float c[4],
                                        const uint32_t a[4],
                                        const uint32_t b[2])
{
    asm volatile(
        "mma.sync.aligned.m16n8k16.row.col.f32.f16.f16.f32 "
        "{%0,%1,%2,%3}, {%4,%5,%6,%7}, {%8,%9}, {%0,%1,%2,%3};\n"
        : "+f"(c[0]), "+f"(c[1]), "+f"(c[2]), "+f"(c[3])
        : "r"(a[0]), "r"(a[1]), "r"(a[2]), "r"(a[3]),
          "r"(b[0]), "r"(b[1]));
}

#define LDMATRIX_X4(r0, r1, r2, r3, addr) \
    asm volatile("ldmatrix.sync.aligned.m8n8.x4.shared.b16 {%0,%1,%2,%3}, [%4];" \
        : "=r"(r0), "=r"(r1), "=r"(r2), "=r"(r3) : "r"(addr))

__device__ __forceinline__ float gemm_epi(float vv, int epi, const float* aux1,
                                          const float* aux2, size_t o)
{
    if (epi == 1) {
        vv = vv / (1.f + expf(-vv));
    } else if (epi == 3) {
        vv = 1.f / (1.f + expf(-vv));
        vv = vv * aux1[o] + aux2[o];
    } else if (epi == 4) {
        vv = vv + aux1[o];
    }
    return vv;
}

__global__ void __launch_bounds__(256, 2)
gemm_hf_kernel(const __half* __restrict__ A, const __half* __restrict__ W,
               float* __restrict__ Co, __half* __restrict__ Coh,
               int Nn, int K, int epi,
               const float* __restrict__ aux1, const float* __restrict__ aux2)
{
    extern __shared__ uint32_t smw[];
    int tid = threadIdx.x;
    int n0 = blockIdx.x * 128;
    int m0 = blockIdx.y * 128;
    int wid = tid >> 5, lane = tid & 31;
    int wm = wid >> 2, wn = wid & 3;
    int gid = lane >> 2, tg = lane & 3;

    // async-copy mapping: row 64 fp16 = 8 chunks of 16B
    int j  = tid & 7;
    int r0 = tid >> 3;           // 0..31, +32*i
    const __half* pA = A + ((size_t)m0 + r0) * K + j * 8;
    const __half* pW = W + ((size_t)n0 + r0) * K + j * 8;
    uint32_t smb = smem_u32(smw);
    uint32_t dstA = smb + (uint32_t)(r0 * 36 + j * 4) * 4u;
    uint32_t dstW = dstA + 4608u * 4u;

    // ldmatrix per-lane base addresses (stage 0, kk=0)
    uint32_t aAddr[4], bAddr[2];
    #pragma unroll
    for (int mi = 0; mi < 4; mi++)
        aAddr[mi] = smb + (uint32_t)((wm * 64 + mi * 16 + (lane & 15)) * 36) * 4u
                        + (uint32_t)(lane >> 4) * 16u;
    #pragma unroll
    for (int p = 0; p < 2; p++)
        bAddr[p] = smb + 4608u * 4u
                 + (uint32_t)((wn * 32 + (p * 2 + (lane >> 4)) * 8 + (lane & 7)) * 36) * 4u
                 + (uint32_t)((lane >> 3) & 1) * 16u;

    float acc[4][4][4];
    #pragma unroll
    for (int mi = 0; mi < 4; mi++)
        #pragma unroll
        for (int ni = 0; ni < 4; ni++)
            #pragma unroll
            for (int e = 0; e < 4; e++) acc[mi][ni][e] = 0.f;

    int NC = K >> 6;

    #pragma unroll
    for (int s = 0; s < 2; s++) {
        uint32_t so = (uint32_t)(s * STG_WORDS) * 4u;
        int kf = s * 64;
        #pragma unroll
        for (int i = 0; i < 4; i++) {
            cp16(dstA + so + (uint32_t)(i * 32 * 36) * 4u, pA + (size_t)(i * 32) * K + kf);
            cp16(dstW + so + (uint32_t)(i * 32 * 36) * 4u, pW + (size_t)(i * 32) * K + kf);
        }
        CP_COMMIT();
    }

    for (int t = 0; t < NC; t++) {
        CP_WAIT_1();
        __syncthreads();
        uint32_t so = (uint32_t)((t & 1) * STG_WORDS) * 4u;

        #pragma unroll
        for (int kk = 0; kk < 4; kk++) {
            uint32_t ko = so + (uint32_t)kk * 32u;    // 8 words per kk
            uint32_t af[4][4];
            uint32_t bf[4][2];
            #pragma unroll
            for (int mi = 0; mi < 4; mi++)
                LDMATRIX_X4(af[mi][0], af[mi][1], af[mi][2], af[mi][3], aAddr[mi] + ko);
            #pragma unroll
            for (int p = 0; p < 2; p++)
                LDMATRIX_X4(bf[2*p][0], bf[2*p][1], bf[2*p+1][0], bf[2*p+1][1], bAddr[p] + ko);
            #pragma unroll
            for (int mi = 0; mi < 4; mi++)
                #pragma unroll
                for (int ni = 0; ni < 4; ni++)
                    mma_f16(acc[mi][ni], af[mi], bf[ni]);
        }
        __syncthreads();

        int lc = t + 2;
        if (lc < NC) {
            uint32_t so2 = (uint32_t)((t & 1) * STG_WORDS) * 4u;
            int kf = lc * 64;
            #pragma unroll
            for (int i = 0; i < 4; i++) {
                cp16(dstA + so2 + (uint32_t)(i * 32 * 36) * 4u, pA + (size_t)(i * 32) * K + kf);
                cp16(dstW + so2 + (uint32_t)(i * 32 * 36) * 4u, pW + (size_t)(i * 32) * K + kf);
            }
        }
        CP_COMMIT();
    }

    // epilogue
    #pragma unroll
    for (int mi = 0; mi < 4; mi++) {
        int row0 = m0 + wm * 64 + mi * 16 + gid;
        #pragma unroll
        for (int ni = 0; ni < 4; ni++) {
            int col0 = n0 + wn * 32 + ni * 8 + tg * 2;
            size_t o0 = (size_t)row0 * Nn + col0;
            size_t o1 = (size_t)(row0 + 8) * Nn + col0;
            if (epi == 2) {
                float a0 = fmaxf(acc[mi][ni][0], 0.f); a0 *= a0;
                float a1 = fmaxf(acc[mi][ni][1], 0.f); a1 *= a1;
                float a2 = fmaxf(acc[mi][ni][2], 0.f); a2 *= a2;
                float a3 = fmaxf(acc[mi][ni][3], 0.f); a3 *= a3;
                *(uint32_t*)(Coh + o0) = pack_f16(a0, a1);
                *(uint32_t*)(Coh + o1) = pack_f16(a2, a3);
            } else {
                float2 v0, v1;
                v0.x = gemm_epi(acc[mi][ni][0], epi, aux1, aux2, o0);
                v0.y = gemm_epi(acc[mi][ni][1], epi, aux1, aux2, o0 + 1);
                v1.x = gemm_epi(acc[mi][ni][2], epi, aux1, aux2, o1);
                v1.y = gemm_epi(acc[mi][ni][3], epi, aux1, aux2, o1 + 1);
                *(float2*)(Co + o0) = v0;
                *(float2*)(Co + o1) = v1;
            }
        }
    }
}

// ---------------- WKV: per-chunk state contribution S = (k*wk) @ v ----------------
__global__ __launch_bounds__(256) void wkv_s_kernel(const float* __restrict__ k,
                                                    const float* __restrict__ v,
                                                    const float* __restrict__ decay,
                                                    float* __restrict__ S)
{
    int blk = blockIdx.x;
    int c = blk % NCK;
    int h = (blk / NCK) % HH;
    int b = blk / (NCK * HH);
    __shared__ float ksm[64][64];
    __shared__ float vsm[64][64];
    __shared__ float wpow[256];
    int tid = threadIdx.x;
    float ew = expf(decay[h]);
    wpow[tid] = expf(-ew * (float)tid);
    int n  = tid >> 2;
    int mg = (tid & 3) * 16;
    float acc[16];
    #pragma unroll
    for (int jj = 0; jj < 16; jj++) acc[jj] = 0.f;

    size_t base = ((size_t)b * TT + (size_t)c * QQ) * CC + (size_t)h * NHD;

    for (int qc = 0; qc < 4; qc++) {
        __syncthreads();
        for (int l = tid; l < 64 * 16; l += 256) {
            int qq = l >> 4;
            int f  = (l & 15) * 4;
            *(float4*)&ksm[qq][f] = *(const float4*)(k + base + (size_t)(qc * 64 + qq) * CC + f);
            *(float4*)&vsm[qq][f] = *(const float4*)(v + base + (size_t)(qc * 64 + qq) * CC + f);
        }
        __syncthreads();
        #pragma unroll 4
        for (int qq = 0; qq < 64; qq++) {
            float kw = ksm[qq][n] * wpow[255 - (qc * 64 + qq)];
            const float4* vr = (const float4*)&vsm[qq][mg];
            float4 v0 = vr[0], v1 = vr[1], v2 = vr[2], v3 = vr[3];
            acc[0]  += kw * v0.x; acc[1]  += kw * v0.y; acc[2]  += kw * v0.z; acc[3]  += kw * v0.w;
            acc[4]  += kw * v1.x; acc[5]  += kw * v1.y; acc[6]  += kw * v1.z; acc[7]  += kw * v1.w;
            acc[8]  += kw * v2.x; acc[9]  += kw * v2.y; acc[10] += kw * v2.z; acc[11] += kw * v2.w;
            acc[12] += kw * v3.x; acc[13] += kw * v3.y; acc[14] += kw * v3.z; acc[15] += kw * v3.w;
        }
    }
    float* Sp = S + (size_t)blk * 4096 + n * 64 + mg;
    #pragma unroll
    for (int jj = 0; jj < 16; jj++) Sp[jj] = acc[jj];
}

// ---------------- WKV: inter-chunk prefix scan ----------------
__global__ __launch_bounds__(256) void wkv_scan_kernel(const float* __restrict__ S,
                                                       const float* __restrict__ decay,
                                                       float* __restrict__ ST)
{
    int bh = blockIdx.x;
    int h = bh % HH;
    float ws = expf(-expf(decay[h]) * 256.0f);
    int tid = threadIdx.x;
    size_t b0 = (size_t)bh * NCK * 4096;
    for (int r = 0; r < 16; r++) {
        int e = tid + r * 256;
        float st = 0.f;
        #pragma unroll
        for (int c = 0; c < NCK; c++) {
            ST[b0 + (size_t)c * 4096 + e] = st;
            st = ws * st + S[b0 + (size_t)c * 4096 + e];
        }
    }
}

// ---------------- WKV: per-chunk output ----------------
#define WKV_Y_SMEM ((256*64*2 + 4096 + 256) * 4)
__global__ __launch_bounds__(256) void wkv_y_kernel(const float* __restrict__ r,
                                                    const float* __restrict__ k,
                                                    const float* __restrict__ v,
                                                    const float* __restrict__ ST,
                                                    const float* __restrict__ decay,
                                                    const float* __restrict__ faaaa,
                                                    float* __restrict__ y)
{
    extern __shared__ float sm[];
    float* ksm  = sm;
    float* vsm  = sm + 16384;
    float* ssm  = sm + 32768;
    float* wpow = sm + 36864;

    int blk = blockIdx.x;
    int c = blk % NCK;
    int h = (blk / NCK) % HH;
    int b = blk / (NCK * HH);
    int tid = threadIdx.x;

    float ew = expf(decay[h]);
    float u  = faaaa[h];
    wpow[tid] = expf(-ew * (float)tid);

    size_t base = ((size_t)b * TT + (size_t)c * QQ) * CC + (size_t)h * NHD;

    for (int l = tid; l < 256 * 16; l += 256) {
        int qq = l >> 4;
        int f  = (l & 15) * 4;
        *(float4*)&ksm[qq * 64 + f] = *(const float4*)(k + base + (size_t)qq * CC + f);
        *(float4*)&vsm[qq * 64 + f] = *(const float4*)(v + base + (size_t)qq * CC + f);
    }
    size_t sbase = (size_t)blk * 4096;
    for (int l = tid; l < 1024; l += 256)
        *(float4*)&ssm[l * 4] = *(const float4*)(ST + sbase + (size_t)l * 4);
    __syncthreads();

    int q = tid;
    float rrow[64];
    {
        const float4* rg = (const float4*)(r + base + (size_t)q * CC);
        #pragma unroll
        for (int f = 0; f < 16; f++) {
            float4 t4 = rg[f];
            rrow[f * 4 + 0] = t4.x; rrow[f * 4 + 1] = t4.y;
            rrow[f * 4 + 2] = t4.z; rrow[f * 4 + 3] = t4.w;
        }
    }
    float acc[64];
    #pragma unroll
    for (int m = 0; m < 64; m++) acc[m] = 0.f;

    #pragma unroll 8
    for (int n = 0; n < 64; n++) {
        float rv = rrow[n];
        const float4* srow = (const float4*)&ssm[n * 64];
        #pragma unroll
        for (int m4 = 0; m4 < 16; m4++) {
            float4 s4 = srow[m4];
            acc[m4 * 4 + 0] += rv * s4.x;
            acc[m4 * 4 + 1] += rv * s4.y;
            acc[m4 * 4 + 2] += rv * s4.z;
            acc[m4 * 4 + 3] += rv * s4.w;
        }
    }
    float wbq = wpow[q];
    #pragma unroll
    for (int m = 0; m < 64; m++) acc[m] *= wbq;

    int jend = q | 31;
    for (int j = 0; j <= jend; j++) {
        float a = 0.f;
        const float4* krow = (const float4*)&ksm[j * 64];
        #pragma unroll
        for (int n4 = 0; n4 < 16; n4++) {
            float4 k4 = krow[n4];
            a += rrow[n4 * 4 + 0] * k4.x + rrow[n4 * 4 + 1] * k4.y
               + rrow[n4 * 4 + 2] * k4.z + rrow[n4 * 4 + 3] * k4.w;
        }
        float coef = (j < q) ? wpow[q - j - 1] : ((j == q) ? u : 0.0f);
        a *= coef;
        const float4* vrow = (const float4*)&vsm[j * 64];
        #pragma unroll
        for (int m4 = 0; m4 < 16; m4++) {
            float4 v4 = vrow[m4];
            acc[m4 * 4 + 0] += a * v4.x;
            acc[m4 * 4 + 1] += a * v4.y;
            acc[m4 * 4 + 2] += a * v4.z;
            acc[m4 * 4 + 3] += a * v4.w;
        }
    }

    float* yo = y + base + (size_t)q * CC;
    #pragma unroll
    for (int m4 = 0; m4 < 16; m4++) {
        float4 o4 = make_float4(acc[m4 * 4 + 0], acc[m4 * 4 + 1], acc[m4 * 4 + 2], acc[m4 * 4 + 3]);
        *(float4*)(yo + m4 * 4) = o4;
    }
}

// ---------------- GroupNorm * g (fp16 output: feeds Wo GEMM) ----------------
__global__ __launch_bounds__(256) void gn_mul_kernel(const float* __restrict__ y,
                                                     const float* __restrict__ gnw,
                                                     const float* __restrict__ gnb,
                                                     const float* __restrict__ g,
                                                     __half* __restrict__ yg)
{
    int row = blockIdx.x;
    int tid = threadIdx.x;
    size_t off = (size_t)row * CC;
    float4 v = ((const float4*)(y + off))[tid];
    float s  = v.x + v.y + v.z + v.w;
    float sq = v.x*v.x + v.y*v.y + v.z*v.z + v.w*v.w;
    #pragma unroll
    for (int o = 8; o >= 1; o >>= 1) {
        s  += __shfl_xor_sync(0xffffffffu, s,  o);
        sq += __shfl_xor_sync(0xffffffffu, sq, o);
    }
    float mu   = s * (1.0f / 64.0f);
    float var  = sq * (1.0f / 64.0f) - mu * mu;
    float rstd = rsqrtf(var + EPS_GN);
    float4 ww = ((const float4*)gnw)[tid];
    float4 bb = ((const float4*)gnb)[tid];
    float4 gg = ((const float4*)(g + off))[tid];
    uint2 o4;
    o4.x = pack_f16(((v.x - mu) * rstd * ww.x + bb.x) * gg.x,
                    ((v.y - mu) * rstd * ww.y + bb.y) * gg.y);
    o4.y = pack_f16(((v.z - mu) * rstd * ww.z + bb.z) * gg.z,
                    ((v.w - mu) * rstd * ww.w + bb.w) * gg.w);
    ((uint2*)(yg + off))[tid] = o4;
}

// ---------------- host launcher ----------------
extern "C" void kernel_launch(void* const* d_in, const int* in_sizes, int n_in,
                              void* d_out, int out_size)
{
    const float* x      = (const float*)d_in[0];
    const float* ln1w   = (const float*)d_in[1];
    const float* ln1b   = (const float*)d_in[2];
    const float* maak   = (const float*)d_in[3];
    const float* maav   = (const float*)d_in[4];
    const float* maar   = (const float*)d_in[5];
    const float* maag   = (const float*)d_in[6];
    const float* decay  = (const float*)d_in[7];
    const float* faaaa  = (const float*)d_in[8];
    const float* Wr     = (const float*)d_in[9];
    const float* Wk     = (const float*)d_in[10];
    const float* Wv     = (const float*)d_in[11];
    const float* Wg     = (const float*)d_in[12];
    const float* Wo     = (const float*)d_in[13];
    const float* gnw    = (const float*)d_in[14];
    const float* gnb    = (const float*)d_in[15];
    const float* ln2w   = (const float*)d_in[16];
    const float* ln2b   = (const float*)d_in[17];
    const float* cmaak  = (const float*)d_in[18];
    const float* cmaar  = (const float*)d_in[19];
    const float* Wck    = (const float*)d_in[20];
    const float* Wcv    = (const float*)d_in[21];
    const float* Wcr    = (const float*)d_in[22];
    float* out = (float*)d_out;

    float* sc = nullptr;
    cudaGetSymbolAddress((void**)&sc, g_scratch);

    __half* xk   = (__half*)(sc + OFF_XK);
    __half* xv   = (__half*)(sc + OFF_XV);
    __half* xr   = (__half*)(sc + OFF_XR);
    __half* xg   = (__half*)(sc + OFF_XG);
    float* rb   = sc + OFF_R;
    float* kb   = sc + OFF_K;
    float* vb   = sc + OFF_V;
    float* gb   = sc + OFF_G;
    float* yb   = sc + OFF_Y;
    __half* ygb = (__half*)(sc + OFF_YG);
    float* x1   = sc + OFF_X1;
    __half* xk2 = (__half*)(sc + OFF_XK2);
    __half* xr2 = (__half*)(sc + OFF_XR2);
    float* hv   = sc + OFF_HV;
    __half* hb  = (__half*)(sc + OFF_H);
    float* Sb   = sc + OFF_S;
    float* STb  = sc + OFF_ST;
    __half* WrR  = (__half*)(sc + OFF_WR_R);
    __half* WkR  = (__half*)(sc + OFF_WK_R);
    __half* WvR  = (__half*)(sc + OFF_WV_R);
    __half* WgR  = (__half*)(sc + OFF_WG_R);
    __half* WoR  = (__half*)(sc + OFF_WO_R);
    __half* WcrR = (__half*)(sc + OFF_WCR_R);
    __half* WckR = (__half*)(sc + OFF_WCK_R);
    __half* WcvR = (__half*)(sc + OFF_WCV_R);

    cudaFuncSetAttribute(wkv_y_kernel, cudaFuncAttributeMaxDynamicSharedMemorySize, WKV_Y_SMEM);
    cudaFuncSetAttribute(gemm_hf_kernel, cudaFuncAttributeMaxDynamicSharedMemorySize, GEMM_SMEM);

    dim3 g1024(1024 / 128, MTOT / 128);   // (8, 128)
    dim3 g3072(3072 / 128, MTOT / 128);   // (24, 128)
    int n4_1M = (CC * CC) / 4;
    int n4_3M = (3 * CC * CC) / 4;

    // ---- time mix ----
    ln_mix_kernel<4><<<MTOT, 256>>>(x, ln1w, ln1b, maak, maav, maar, maag, xk, xv, xr, xg);
    cvt_w_kernel<<<n4_1M / 256, 256>>>(Wr, WrR, n4_1M);
    cvt_w_kernel<<<n4_1M / 256, 256>>>(Wk, WkR, n4_1M);
    cvt_w_kernel<<<n4_1M / 256, 256>>>(Wv, WvR, n4_1M);
    cvt_w_kernel<<<n4_1M / 256, 256>>>(Wg, WgR, n4_1M);
    gemm_hf_kernel<<<g1024, 256, GEMM_SMEM>>>(xr, WrR, rb, nullptr, 1024, 1024, 0, nullptr, nullptr);
    gemm_hf_kernel<<<g1024, 256, GEMM_SMEM>>>(xk, WkR, kb, nullptr, 1024, 1024, 0, nullptr, nullptr);
    gemm_hf_kernel<<<g1024, 256, GEMM_SMEM>>>(xv, WvR, vb, nullptr, 1024, 1024, 0, nullptr, nullptr);
    gemm_hf_kernel<<<g1024, 256, GEMM_SMEM>>>(xg, WgR, gb, nullptr, 1024, 1024, 1, nullptr, nullptr); // silu

    wkv_s_kernel<<<BB * HH * NCK, 256>>>(kb, vb, decay, Sb);
    wkv_scan_kernel<<<BB * HH, 256>>>(Sb, decay, STb);
    wkv_y_kernel<<<BB * HH * NCK, 256, WKV_Y_SMEM>>>(rb, kb, vb, STb, decay, faaaa, yb);

    gn_mul_kernel<<<MTOT, 256>>>(yb, gnw, gnb, gb, ygb);
    cvt_w_kernel<<<n4_1M / 256, 256>>>(Wo, WoR, n4_1M);
    gemm_hf_kernel<<<g1024, 256, GEMM_SMEM>>>(ygb, WoR, x1, nullptr, 1024, 1024, 4, x, nullptr); // + residual

    // ---- channel mix ----
    ln_mix_kernel<2><<<MTOT, 256>>>(x1, ln2w, ln2b, cmaak, cmaar, nullptr, nullptr,
                                    xk2, xr2, nullptr, nullptr);
    cvt_w_kernel<<<n4_3M / 256, 256>>>(Wck, WckR, n4_3M);
    cvt_w_kernel<<<n4_3M / 256, 256>>>(Wcv, WcvR, n4_3M);
    cvt_w_kernel<<<n4_1M / 256, 256>>>(Wcr, WcrR, n4_1M);
    gemm_hf_kernel<<<g3072, 256, GEMM_SMEM>>>(xk2, WckR, nullptr, hb, 3072, 1024, 2, nullptr, nullptr); // relu^2 -> fp16
    gemm_hf_kernel<<<g1024, 256, GEMM_SMEM>>>(hb, WcvR, hv, nullptr, 1024, 3072, 0, nullptr, nullptr);
    gemm_hf_kernel<<<g1024, 256, GEMM_SMEM>>>(xr2, WcrR, out, nullptr, 1024, 1024, 3, hv, x1); // sigmoid*hv + x1
}